// round 10
// baseline (speedup 1.0000x reference)
#include <cuda_runtime.h>
#include <cuda_bf16.h>
#include <mma.h>
using namespace nvcuda;

#define B_  32
#define T_  64
#define S_  64
#define H_  512
#define D_  512
#define V_  32000
#define G4_ 2048            // 4*H
#define MR_ 2048            // T*B rows

#define CTAS_ 128
#define UPC_  4             // units per CTA (both layers)

// d_out layout (f32): log_probs [T,B,V], hT [2,B,H], cT [2,B,H], attn [B,S]
#define OFF_HT   ((size_t)T_ * B_ * V_)
#define OFF_CT   (OFF_HT + (size_t)2 * B_ * H_)
#define OFF_ATTN (OFF_CT + (size_t)2 * B_ * H_)

// ---------------- device scratch -------------------------------------------
__device__ float g_pre0[(size_t)T_ * G4_ * B_];       // [t][gate_row][b]  16MB
__device__ float g_c2[(size_t)B_ * S_ * H_];          // context @ W_attn_in 4MB
__device__ float g_h0[2][B_ * H_];                    // h layer0, [b][k] row-major
__device__ float g_h1[2][B_ * H_];                    // h layer1, [b][k] row-major
__device__ float4 g_cat4[(2 * H_ / 4) * B_];          // [ctx ; h1] k4 layout
__device__ __nv_bfloat16 g_outs_bf[(size_t)MR_ * H_];
__device__ __nv_bfloat16 g_wlin_bf[(size_t)V_ * D_];
__device__ unsigned g_bar;

__device__ __forceinline__ float sigf(float x) { return 1.f / (1.f + __expf(-x)); }
__device__ __forceinline__ float totf(float x) { return wmma::__float_to_tf32(x); }

__global__ void k_reset() { g_bar = 0u; }

// ---------------- W_lin fp32 -> bf16 ---------------------------------------
__global__ void k_convert_wlin(const float* __restrict__ w) {
    int i = blockIdx.x * blockDim.x + threadIdx.x;
    if (i < (V_ * D_) / 4) {
        float4 v = reinterpret_cast<const float4*>(w)[i];
        __nv_bfloat162* o = reinterpret_cast<__nv_bfloat162*>(g_wlin_bf);
        o[i * 2]     = __floats2bfloat162_rn(v.x, v.y);
        o[i * 2 + 1] = __floats2bfloat162_rn(v.z, v.w);
    }
}

// ---------------- embed + input projection (tf32 WMMA) ----------------------
__global__ void __launch_bounds__(256)
k_gemm_pre(const int* __restrict__ tokens,
           const float* __restrict__ embedding,
           const float* __restrict__ Wih0,
           const float* __restrict__ bih0,
           const float* __restrict__ bhh0) {
    __shared__ float As[128 * 36];
    __shared__ float Bs[128 * 36];
    __shared__ float scr[8 * 320];        // per-warp 16x16 frag scratch, ldm 20
    __shared__ float bsh[128];
    __shared__ int   toks[128];
    const int tid = threadIdx.x;
    const int w   = tid >> 5;
    const int lane = tid & 31;
    const int m0 = blockIdx.y * 128, n0 = blockIdx.x * 128;
    const int wm = (w >> 2) * 64, wn = (w & 3) * 32;

    if (tid < 128) {
        int m = m0 + tid;
        toks[tid] = tokens[(m & 31) * T_ + (m >> 5)];
        bsh[tid] = bih0[n0 + tid] + bhh0[n0 + tid];
    }
    __syncthreads();

    wmma::fragment<wmma::accumulator, 16, 16, 8, float> acc[4][2];
#pragma unroll
    for (int i = 0; i < 4; i++)
#pragma unroll
        for (int j = 0; j < 2; j++) wmma::fill_fragment(acc[i][j], 0.f);

    for (int k0 = 0; k0 < D_; k0 += 32) {
#pragma unroll
        for (int it = 0; it < 4; it++) {
            int idx = tid + it * 256;        // 1024 f4 slots: 128 rows x 8 f4
            int r = idx >> 3, c = (idx & 7) * 4;
            float4 va = *reinterpret_cast<const float4*>(
                embedding + (size_t)toks[r] * D_ + k0 + c);
            As[r * 36 + c] = totf(va.x); As[r * 36 + c + 1] = totf(va.y);
            As[r * 36 + c + 2] = totf(va.z); As[r * 36 + c + 3] = totf(va.w);
            float4 vb = *reinterpret_cast<const float4*>(
                Wih0 + (size_t)(n0 + r) * D_ + k0 + c);
            Bs[r * 36 + c] = totf(vb.x); Bs[r * 36 + c + 1] = totf(vb.y);
            Bs[r * 36 + c + 2] = totf(vb.z); Bs[r * 36 + c + 3] = totf(vb.w);
        }
        __syncthreads();
#pragma unroll
        for (int kk = 0; kk < 4; kk++) {
            wmma::fragment<wmma::matrix_b, 16, 16, 8, wmma::precision::tf32, wmma::col_major> b[2];
#pragma unroll
            for (int j = 0; j < 2; j++)
                wmma::load_matrix_sync(b[j], Bs + (wn + j * 16) * 36 + kk * 8, 36);
#pragma unroll
            for (int i = 0; i < 4; i++) {
                wmma::fragment<wmma::matrix_a, 16, 16, 8, wmma::precision::tf32, wmma::row_major> a;
                wmma::load_matrix_sync(a, As + (wm + i * 16) * 36 + kk * 8, 36);
#pragma unroll
                for (int j = 0; j < 2; j++) wmma::mma_sync(acc[i][j], a, b[j], acc[i][j]);
            }
        }
        __syncthreads();
    }
#pragma unroll
    for (int i = 0; i < 4; i++)
#pragma unroll
        for (int j = 0; j < 2; j++) {
            wmma::store_matrix_sync(scr + w * 320, acc[i][j], 20, wmma::mem_row_major);
            __syncwarp();
            int c = lane >> 1;                    // 0..15 (n within frag)
            int r0 = (lane & 1) * 8;              // 0 or 8
            int n = n0 + wn + j * 16 + c;
            int mbase = m0 + wm + i * 16 + r0;
            int t = mbase >> 5, b0 = mbase & 31;
            float bias = bsh[wn + j * 16 + c];
            float* dst = g_pre0 + ((size_t)t * G4_ + n) * B_ + b0;
#pragma unroll
            for (int rr = 0; rr < 8; rr++)
                dst[rr] = scr[w * 320 + (r0 + rr) * 20 + c] + bias;
            __syncwarp();
        }
}

// ---------------- C2 = context @ W_attn_in (tf32 WMMA) ----------------------
__global__ void __launch_bounds__(256)
k_c2(const float* __restrict__ A, const float* __restrict__ Wq) {
    __shared__ float As[128 * 36];
    __shared__ float Bs[32 * 132];
    const int tid = threadIdx.x;
    const int w   = tid >> 5;
    const int m0 = blockIdx.y * 128, n0 = blockIdx.x * 128;
    const int wm = (w >> 2) * 64, wn = (w & 3) * 32;

    wmma::fragment<wmma::accumulator, 16, 16, 8, float> acc[4][2];
#pragma unroll
    for (int i = 0; i < 4; i++)
#pragma unroll
        for (int j = 0; j < 2; j++) wmma::fill_fragment(acc[i][j], 0.f);

    for (int k0 = 0; k0 < H_; k0 += 32) {
#pragma unroll
        for (int it = 0; it < 4; it++) {     // A: 128 rows x 8 f4
            int idx = tid + it * 256;
            int r = idx >> 3, c = (idx & 7) * 4;
            float4 va = *reinterpret_cast<const float4*>(
                A + (size_t)(m0 + r) * H_ + k0 + c);
            As[r * 36 + c] = totf(va.x); As[r * 36 + c + 1] = totf(va.y);
            As[r * 36 + c + 2] = totf(va.z); As[r * 36 + c + 3] = totf(va.w);
        }
#pragma unroll
        for (int it = 0; it < 4; it++) {     // B: 32 rows x 32 f4 (128 n)
            int idx = tid + it * 256;
            int r = idx >> 5, c = (idx & 31) * 4;
            float4 vb = *reinterpret_cast<const float4*>(
                Wq + (size_t)(k0 + r) * H_ + n0 + c);
            Bs[r * 132 + c] = totf(vb.x); Bs[r * 132 + c + 1] = totf(vb.y);
            Bs[r * 132 + c + 2] = totf(vb.z); Bs[r * 132 + c + 3] = totf(vb.w);
        }
        __syncthreads();
#pragma unroll
        for (int kk = 0; kk < 4; kk++) {
            wmma::fragment<wmma::matrix_b, 16, 16, 8, wmma::precision::tf32, wmma::row_major> b[2];
#pragma unroll
            for (int j = 0; j < 2; j++)
                wmma::load_matrix_sync(b[j], Bs + kk * 8 * 132 + wn + j * 16, 132);
#pragma unroll
            for (int i = 0; i < 4; i++) {
                wmma::fragment<wmma::matrix_a, 16, 16, 8, wmma::precision::tf32, wmma::row_major> a;
                wmma::load_matrix_sync(a, As + (wm + i * 16) * 36 + kk * 8, 36);
#pragma unroll
                for (int j = 0; j < 2; j++) wmma::mma_sync(acc[i][j], a, b[j], acc[i][j]);
            }
        }
        __syncthreads();
    }
#pragma unroll
    for (int i = 0; i < 4; i++)
#pragma unroll
        for (int j = 0; j < 2; j++)
            wmma::store_matrix_sync(g_c2 + (size_t)(m0 + wm + i * 16) * H_ + n0 + wn + j * 16,
                                    acc[i][j], H_, wmma::mem_row_major);
}

// ---------------- persistent scan kernel (tf32 WMMA for L0/L1) --------------
// SMEM float offsets
#define SM_W0    0                          // 16 x 520
#define SM_W1    8320                       // 16 x 1040
#define SM_WOS   24960                      // 4 x 1024
#define SM_STAGE 29056                      // 32 x 520
#define SM_PBUF  45696                      // 8 x 256 wmma partials
#define SM_GBUF  47744                      // 16 x 32
#define SM_CB    48256                      // 2 x 4 x 32
#define SM_B1    48512                      // 16
#define SM_PART  48528                      // 8 x 32
#define SMEM_FLOATS 48784
#define SMEM_BYTES  (SMEM_FLOATS * 4)

#define LDW0  520
#define LDW1  1040
#define LDST  520

__device__ __forceinline__ void gridbar(unsigned target) {
    __threadfence();
    __syncthreads();
    if (threadIdx.x == 0) {
        atomicAdd(&g_bar, 1u);
        volatile unsigned* vb = &g_bar;
        while (*vb < target) { }
    }
    __syncthreads();
}

// copy 32x512 row-major h into padded stage [b][520], rounding to tf32
__device__ __forceinline__ void stage_rows(float* stg, const float4* src, int tid) {
    for (int idx = tid; idx < 4096; idx += 256) {
        int b = idx >> 7, j = idx & 127;
        float4 v = __ldcg(&src[idx]);
        v.x = totf(v.x); v.y = totf(v.y); v.z = totf(v.z); v.w = totf(v.w);
        reinterpret_cast<float4*>(stg + b * LDST)[j] = v;
    }
}

__global__ void __launch_bounds__(256, 1)
k_scan(const float* __restrict__ Whh0, const float* __restrict__ Wih1,
       const float* __restrict__ Whh1, const float* __restrict__ bih,
       const float* __restrict__ bhh, const float* __restrict__ context,
       const float* __restrict__ Wout, const float* __restrict__ h0in,
       const float* __restrict__ c0in, float* __restrict__ out) {
    extern __shared__ float sm[];
    float*  W0s   = sm + SM_W0;
    float*  W1s   = sm + SM_W1;
    float*  Wos   = sm + SM_WOS;
    float*  stg   = sm + SM_STAGE;
    float*  pbuf  = sm + SM_PBUF;
    float*  gbuf  = sm + SM_GBUF;
    float*  cb    = sm + SM_CB;
    float*  bias1 = sm + SM_B1;
    float*  part  = sm + SM_PART;

    const int cta = blockIdx.x;
    const int tid = threadIdx.x;
    const int w   = tid >> 5;
    const int lane = tid & 31;
    const int u0  = cta * UPC_;
    const int wn  = w & 1;            // n-tile (batch 16s)
    const int wkc = w >> 1;           // k-chunk (128s)
    const int ab  = cta & 31;         // attention batch
    const int aq  = cta >> 5;         // attention quarter (0..3)

    // -------- prologue: weights -> SMEM (pre-rounded to tf32) --------------
    for (int idx = tid; idx < 16 * 128; idx += 256) {
        int r = idx >> 7, kq = idx & 127;
        int row = ((r >> 2) * H_) + u0 + (r & 3);
        float4 v = *reinterpret_cast<const float4*>(Whh0 + (size_t)row * H_ + kq * 4);
        v.x = totf(v.x); v.y = totf(v.y); v.z = totf(v.z); v.w = totf(v.w);
        reinterpret_cast<float4*>(W0s + r * LDW0)[kq] = v;
    }
    for (int idx = tid; idx < 16 * 256; idx += 256) {
        int r = idx >> 8, kq = idx & 255;
        int row = ((r >> 2) * H_) + u0 + (r & 3);
        const float* src = (kq < 128)
            ? (Wih1 + (size_t)row * H_ + kq * 4)
            : (Whh1 + (size_t)row * H_ + (kq - 128) * 4);
        float4 v = *reinterpret_cast<const float4*>(src);
        v.x = totf(v.x); v.y = totf(v.y); v.z = totf(v.z); v.w = totf(v.w);
        reinterpret_cast<float4*>(W1s + r * LDW1)[kq] = v;
    }
    for (int idx = tid; idx < 4 * 256; idx += 256) {     // Wos stays fp32
        int r = idx >> 8, kq = idx & 255;
        reinterpret_cast<float4*>(Wos + r * 1024)[kq] =
            *reinterpret_cast<const float4*>(Wout + (size_t)(u0 + r) * (2 * H_) + kq * 4);
    }
    if (tid < 16) {
        int row = ((tid >> 2) * H_) + u0 + (tid & 3);
        bias1[tid] = bih[G4_ + row] + bhh[G4_ + row];
    }
    {   // cell state: cb[l*128 + ul*32 + b]
        int l = tid >> 7, ul = (tid >> 5) & 3, b = tid & 31;
        cb[tid] = c0in[(size_t)l * B_ * H_ + (size_t)b * H_ + u0 + ul];
    }
    if (tid < 32) {   // initial h -> row-major global
        int b = tid;
#pragma unroll
        for (int ul = 0; ul < 4; ul++) {
            __stcg(&g_h0[0][b * H_ + u0 + ul], h0in[(size_t)b * H_ + u0 + ul]);
            __stcg(&g_h1[0][b * H_ + u0 + ul], h0in[(size_t)B_ * H_ + b * H_ + u0 + ul]);
        }
    }
    unsigned nbar = 0;
    gridbar(++nbar * CTAS_);
    stage_rows(stg, reinterpret_cast<const float4*>(g_h0[0]), tid);
    __syncthreads();

    // -------- main scan ----------------------------------------------------
    for (int t = 0; t < T_; t++) {
        const int p = t & 1;

        // ===== layer 0: stg pre-staged with h0old (tf32) =====
        {
            wmma::fragment<wmma::accumulator, 16, 16, 8, float> c;
            wmma::fill_fragment(c, 0.f);
#pragma unroll
            for (int kk = 0; kk < 16; kk++) {
                int k = wkc * 128 + kk * 8;
                wmma::fragment<wmma::matrix_a, 16, 16, 8, wmma::precision::tf32, wmma::row_major> a;
                wmma::fragment<wmma::matrix_b, 16, 16, 8, wmma::precision::tf32, wmma::col_major> b;
                wmma::load_matrix_sync(a, W0s + k, LDW0);
                wmma::load_matrix_sync(b, stg + (wn * 16) * LDST + k, LDST);
                wmma::mma_sync(c, a, b, c);
            }
            wmma::store_matrix_sync(pbuf + w * 256, c, 16, wmma::mem_row_major);
        }
        __syncthreads();
        for (int o = tid; o < 512; o += 256) {          // reduce 4 k-chunks
            int r = o >> 5, b = o & 31;
            float s = 0.f;
#pragma unroll
            for (int kc = 0; kc < 4; kc++)
                s += pbuf[((b >> 4) + 2 * kc) * 256 + r * 16 + (b & 15)];
            gbuf[r * 32 + b] = s;
        }
        __syncthreads();
        if (tid < 128) {
            int ul = tid >> 5, b = tid & 31, u = u0 + ul;
            const float* pre = g_pre0 + (size_t)t * G4_ * B_;
            float gi = sigf(gbuf[(0  + ul) * 32 + b] + __ldg(&pre[((size_t)0 * H_ + u) * B_ + b]));
            float gf = sigf(gbuf[(4  + ul) * 32 + b] + __ldg(&pre[((size_t)1 * H_ + u) * B_ + b]));
            float gg = tanhf(gbuf[(8  + ul) * 32 + b] + __ldg(&pre[((size_t)2 * H_ + u) * B_ + b]));
            float go = sigf(gbuf[(12 + ul) * 32 + b] + __ldg(&pre[((size_t)3 * H_ + u) * B_ + b]));
            float c = gf * cb[ul * 32 + b] + gi * gg;
            cb[ul * 32 + b] = c;
            float h = go * tanhf(c);
            __stcg(&g_h0[p ^ 1][b * H_ + u], h);
            if (t == T_ - 1) {
                out[OFF_HT + (size_t)b * H_ + u] = h;
                out[OFF_CT + (size_t)b * H_ + u] = c;
            }
        }
        gridbar(++nbar * CTAS_);

        // ===== layer 1: two K passes (x = h0new, then h1old), tf32 wmma =====
        {
            wmma::fragment<wmma::accumulator, 16, 16, 8, float> c;
            wmma::fill_fragment(c, 0.f);
#pragma unroll
            for (int pass = 0; pass < 2; pass++) {
                const float4* src = pass ? reinterpret_cast<const float4*>(g_h1[p])
                                         : reinterpret_cast<const float4*>(g_h0[p ^ 1]);
                stage_rows(stg, src, tid);
                __syncthreads();
                const int koff = pass * 512;
#pragma unroll
                for (int kk = 0; kk < 16; kk++) {
                    int k = wkc * 128 + kk * 8;
                    wmma::fragment<wmma::matrix_a, 16, 16, 8, wmma::precision::tf32, wmma::row_major> a;
                    wmma::fragment<wmma::matrix_b, 16, 16, 8, wmma::precision::tf32, wmma::col_major> b;
                    wmma::load_matrix_sync(a, W1s + koff + k, LDW1);
                    wmma::load_matrix_sync(b, stg + (wn * 16) * LDST + k, LDST);
                    wmma::mma_sync(c, a, b, c);
                }
                __syncthreads();   // stage reuse between passes
            }
            wmma::store_matrix_sync(pbuf + w * 256, c, 16, wmma::mem_row_major);
        }
        __syncthreads();
        for (int o = tid; o < 512; o += 256) {
            int r = o >> 5, b = o & 31;
            float s = 0.f;
#pragma unroll
            for (int kc = 0; kc < 4; kc++)
                s += pbuf[((b >> 4) + 2 * kc) * 256 + r * 16 + (b & 15)];
            gbuf[r * 32 + b] = s;
        }
        __syncthreads();
        if (tid < 128) {
            int ul = tid >> 5, b = tid & 31, u = u0 + ul;
            float gi = sigf(gbuf[(0  + ul) * 32 + b] + bias1[0  + ul]);
            float gf = sigf(gbuf[(4  + ul) * 32 + b] + bias1[4  + ul]);
            float gg = tanhf(gbuf[(8  + ul) * 32 + b] + bias1[8  + ul]);
            float go = sigf(gbuf[(12 + ul) * 32 + b] + bias1[12 + ul]);
            float c = gf * cb[128 + ul * 32 + b] + gi * gg;
            cb[128 + ul * 32 + b] = c;
            float h = go * tanhf(c);
            __stcg(&g_h1[p ^ 1][b * H_ + u], h);
            if (t == T_ - 1) {
                out[OFF_HT + (size_t)B_ * H_ + (size_t)b * H_ + u] = h;
                out[OFF_CT + (size_t)B_ * H_ + (size_t)b * H_ + u] = c;
            }
        }
        gridbar(++nbar * CTAS_);

        // ===== attention: ALL 128 CTAs; b = cta&31, quarter = cta>>5 =====
        {
            float* qs  = stg;                  // 512
            float* sc  = qs + 512;             // 64
            float* att = sc + 64;              // 64
            const float4* h1row = reinterpret_cast<const float4*>(g_h1[p ^ 1] + ab * H_);
            for (int q = tid; q < 128; q += 256)
                reinterpret_cast<float4*>(qs)[q] = __ldcg(&h1row[q]);
            __syncthreads();
            {   // scores: warp w handles s = w*8 .. w*8+7 (duplicated across quarters)
                const float4* qs4 = reinterpret_cast<const float4*>(qs);
#pragma unroll
                for (int si = 0; si < 8; si++) {
                    int s = w * 8 + si;
                    const float4* c2r = reinterpret_cast<const float4*>(
                        g_c2 + (size_t)(ab * S_ + s) * H_);
                    float a = 0.f;
#pragma unroll
                    for (int kq = lane; kq < 128; kq += 32) {
                        float4 cv = __ldg(&c2r[kq]);
                        float4 qv = qs4[kq];
                        a += cv.x * qv.x + cv.y * qv.y + cv.z * qv.z + cv.w * qv.w;
                    }
#pragma unroll
                    for (int off = 16; off; off >>= 1) a += __shfl_xor_sync(0xffffffffu, a, off);
                    if (lane == 0) sc[s] = a;
                }
            }
            __syncthreads();
            if (tid < 32) {
                float v0 = sc[tid], v1 = sc[tid + 32];
                float m = fmaxf(v0, v1);
#pragma unroll
                for (int off = 16; off; off >>= 1) m = fmaxf(m, __shfl_xor_sync(0xffffffffu, m, off));
                float e0 = __expf(v0 - m), e1 = __expf(v1 - m);
                float s2 = e0 + e1;
#pragma unroll
                for (int off = 16; off; off >>= 1) s2 += __shfl_xor_sync(0xffffffffu, s2, off);
                float inv = 1.f / s2;
                att[tid] = e0 * inv; att[tid + 32] = e1 * inv;
                if (aq == 0 && t == T_ - 1) {
                    out[OFF_ATTN + ab * S_ + tid]      = e0 * inv;
                    out[OFF_ATTN + ab * S_ + tid + 32] = e1 * inv;
                }
            }
            __syncthreads();
            {   // ctx: quarter handles h in [aq*128, aq*128+128); 2 threads per h
                int h = aq * 128 + (tid >> 1);
                int s0 = (tid & 1) * 32;
                const float* cx = context + (size_t)ab * S_ * H_ + h;
                float a = 0.f;
#pragma unroll 8
                for (int s = s0; s < s0 + 32; s++) a += att[s] * cx[(size_t)s * H_];
                a += __shfl_xor_sync(0xffffffffu, a, 1);
                if ((tid & 1) == 0) {
                    __stcg(&reinterpret_cast<float*>(g_cat4)[((h >> 2) * 32 + ab) * 4 + (h & 3)], a);
                    int h2 = H_ + h;
                    __stcg(&reinterpret_cast<float*>(g_cat4)[((h2 >> 2) * 32 + ab) * 4 + (h2 & 3)], qs[h]);
                }
            }
        }
        gridbar(++nbar * CTAS_);

        // ===== attention-out: direct L2 reads of g_cat4 (each elem read once);
        //       overlapped with prefetch of next step's L0 stage =====
        {
            float oa = 0.f, ob = 0.f;
            const int row = w & 3, sub = w >> 2;
            const int i0 = sub * 64;
#pragma unroll
            for (int half = 0; half < 2; half++) {
                const float4* wr = reinterpret_cast<const float4*>(Wos + row * 1024 + half * H_);
                const float4* catp = g_cat4 + half * 4096;
#pragma unroll 4
                for (int i = 0; i < 64; i++) {
                    float4 h = __ldcg(&catp[(i0 + i) * 32 + lane]);
                    float4 x = wr[i0 + i];
                    oa += x.x * h.x + x.y * h.y;
                    ob += x.z * h.z + x.w * h.w;
                }
            }
            part[w * 32 + lane] = oa + ob;
        }
        // prefetch next L0 stage (h0 state p^1, produced this step, visible since bar1)
        stage_rows(stg, reinterpret_cast<const float4*>(g_h0[p ^ 1]), tid);
        __syncthreads();
        if (tid < 128) {
            int r = tid >> 5, b = tid & 31;
            float v = tanhf(part[r * 32 + b] + part[(r + 4) * 32 + b]);
            g_outs_bf[((size_t)t * B_ + b) * H_ + u0 + r] = __float2bfloat16(v);
        }
    }
}

// ---------------- vocab GEMM: logits = outs_bf @ wlin_bf^T ------------------
// double-buffered SMEM, register prefetch; k-tile 32
__global__ void __launch_bounds__(256)
k_wmma(float* __restrict__ C) {
    __shared__ __align__(16) __nv_bfloat16 As[2][128 * 40];
    __shared__ __align__(16) __nv_bfloat16 Bs[2][128 * 40];
    const int m0 = blockIdx.y * 128, n0 = blockIdx.x * 128;
    const int tid = threadIdx.x;                  // 256
    const int wid = tid >> 5;
    const int wm = (wid >> 2) * 64, wn = (wid & 3) * 32;
    wmma::fragment<wmma::accumulator, 16, 16, 16, float> acc[4][2];
#pragma unroll
    for (int i = 0; i < 4; i++)
#pragma unroll
        for (int j = 0; j < 2; j++) wmma::fill_fragment(acc[i][j], 0.f);
    const int r = tid >> 1;
    const int c = (tid & 1) * 16;

    // preload tile 0
#pragma unroll
    for (int q = 0; q < 2; q++) {
        *reinterpret_cast<uint4*>(&As[0][r * 40 + c + q * 8]) =
            *reinterpret_cast<const uint4*>(&g_outs_bf[(size_t)(m0 + r) * D_ + c + q * 8]);
        *reinterpret_cast<uint4*>(&Bs[0][r * 40 + c + q * 8]) =
            *reinterpret_cast<const uint4*>(&g_wlin_bf[(size_t)(n0 + r) * D_ + c + q * 8]);
    }
    __syncthreads();

    int buf = 0;
    for (int k0 = 0; k0 < D_; k0 += 32) {
        uint4 ra[2], rb[2];
        const bool has_next = (k0 + 32 < D_);
        if (has_next) {
#pragma unroll
            for (int q = 0; q < 2; q++) {
                ra[q] = *reinterpret_cast<const uint4*>(
                    &g_outs_bf[(size_t)(m0 + r) * D_ + k0 + 32 + c + q * 8]);
                rb[q] = *reinterpret_cast<const uint4*>(
                    &g_wlin_bf[(size_t)(n0 + r) * D_ + k0 + 32 + c + q * 8]);
            }
        }
#pragma unroll
        for (int sub = 0; sub < 2; sub++) {
            wmma::fragment<wmma::matrix_b, 16, 16, 16, __nv_bfloat16, wmma::col_major> bf[2];
#pragma unroll
            for (int j = 0; j < 2; j++)
                wmma::load_matrix_sync(bf[j], &Bs[buf][(wn + j * 16) * 40 + sub * 16], 40);
#pragma unroll
            for (int i = 0; i < 4; i++) {
                wmma::fragment<wmma::matrix_a, 16, 16, 16, __nv_bfloat16, wmma::row_major> af;
                wmma::load_matrix_sync(af, &As[buf][(wm + i * 16) * 40 + sub * 16], 40);
#pragma unroll
                for (int j = 0; j < 2; j++) wmma::mma_sync(acc[i][j], af, bf[j], acc[i][j]);
            }
        }
        if (has_next) {
#pragma unroll
            for (int q = 0; q < 2; q++) {
                *reinterpret_cast<uint4*>(&As[buf ^ 1][r * 40 + c + q * 8]) = ra[q];
                *reinterpret_cast<uint4*>(&Bs[buf ^ 1][r * 40 + c + q * 8]) = rb[q];
            }
        }
        __syncthreads();
        buf ^= 1;
    }
#pragma unroll
    for (int i = 0; i < 4; i++)
#pragma unroll
        for (int j = 0; j < 2; j++)
            wmma::store_matrix_sync(C + (size_t)(m0 + wm + i * 16) * V_ + n0 + wn + j * 16,
                                    acc[i][j], V_, wmma::mem_row_major);
}

// ---------------- log_softmax (adds b_lin, in-place, float4 vectorized) -----
__global__ void k_logsoftmax(float* __restrict__ logits, const float* __restrict__ b_lin) {
    const int row = blockIdx.x;
    float* p = logits + (size_t)row * V_;
    float4* p4 = reinterpret_cast<float4*>(p);
    const float4* b4 = reinterpret_cast<const float4*>(b_lin);
    const int tid = threadIdx.x;
    float m = -1e30f, s = 0.f;
    for (int v = tid; v < V_ / 4; v += 256) {
        float4 x = p4[v], bb = b4[v];
        float e[4] = {x.x + bb.x, x.y + bb.y, x.z + bb.z, x.w + bb.w};
#pragma unroll
        for (int q = 0; q < 4; q++) {
            if (e[q] > m) { s = s * __expf(m - e[q]) + 1.f; m = e[q]; }
            else          { s += __expf(e[q] - m); }
        }
    }
    __shared__ float sm[256], ss[256];
    sm[tid] = m; ss[tid] = s;
    __syncthreads();
    for (int off = 128; off; off >>= 1) {
        if (tid < off) {
            float m2 = sm[tid + off], s2 = ss[tid + off];
            float M = fmaxf(sm[tid], m2);
            ss[tid] = ss[tid] * __expf(sm[tid] - M) + s2 * __expf(m2 - M);
            sm[tid] = M;
        }
        __syncthreads();
    }
    float lse = sm[0] + logf(ss[0]);
    for (int v = tid; v < V_ / 4; v += 256) {
        float4 x = p4[v], bb = b4[v];
        x.x = x.x + bb.x - lse; x.y = x.y + bb.y - lse;
        x.z = x.z + bb.z - lse; x.w = x.w + bb.w - lse;
        p4[v] = x;
    }
}

// ---------------- host driver ----------------------------------------------
extern "C" void kernel_launch(void* const* d_in, const int* in_sizes, int n_in,
                              void* d_out, int out_size) {
    const int*   tokens     = (const int*)d_in[0];
    const float* h0         = (const float*)d_in[1];
    const float* c0         = (const float*)d_in[2];
    const float* context    = (const float*)d_in[3];
    const float* embedding  = (const float*)d_in[4];
    const float* Wih        = (const float*)d_in[5];
    const float* Whh        = (const float*)d_in[6];
    const float* bih        = (const float*)d_in[7];
    const float* bhh        = (const float*)d_in[8];
    const float* W_attn_in  = (const float*)d_in[9];
    const float* W_attn_out = (const float*)d_in[10];
    const float* W_lin      = (const float*)d_in[11];
    const float* b_lin      = (const float*)d_in[12];
    float* out = (float*)d_out;

    cudaFuncSetAttribute(k_scan, cudaFuncAttributeMaxDynamicSharedMemorySize, SMEM_BYTES);

    const float* Wih1 = Wih + (size_t)G4_ * D_;
    const float* Whh1 = Whh + (size_t)G4_ * H_;

    k_reset<<<1, 1>>>();
    k_convert_wlin<<<(V_ * D_ / 4 + 255) / 256, 256>>>(W_lin);
    k_gemm_pre<<<dim3(G4_ / 128, MR_ / 128), 256>>>(tokens, embedding, Wih, bih, bhh);
    k_c2<<<dim3(H_ / 128, (B_ * S_) / 128), 256>>>(context, W_attn_in);
    k_scan<<<CTAS_, 256, SMEM_BYTES>>>(Whh, Wih1, Whh1, bih, bhh, context,
                                       W_attn_out, h0, c0, out);
    k_wmma<<<dim3(V_ / 128, MR_ / 128), 256>>>(out);
    k_logsoftmax<<<MR_, 256>>>(out, b_lin);
}

// round 11
// speedup vs baseline: 1.0587x; 1.0587x over previous
#include <cuda_runtime.h>
#include <cuda_bf16.h>
#include <mma.h>
using namespace nvcuda;

#define B_  32
#define T_  64
#define S_  64
#define H_  512
#define D_  512
#define V_  32000
#define G4_ 2048            // 4*H
#define MR_ 2048            // T*B rows

#define CTAS_ 128
#define UPC_  4             // units per CTA (both layers)
#define NT_   67            // pipelined ticks = T + 3

// d_out layout (f32): log_probs [T,B,V], hT [2,B,H], cT [2,B,H], attn [B,S]
#define OFF_HT   ((size_t)T_ * B_ * V_)
#define OFF_CT   (OFF_HT + (size_t)2 * B_ * H_)
#define OFF_ATTN (OFF_CT + (size_t)2 * B_ * H_)

// ---------------- device scratch -------------------------------------------
__device__ float g_pre0[(size_t)T_ * G4_ * B_];       // [t][gate_row][b]  16MB
__device__ float g_c2[(size_t)B_ * S_ * H_];          // context @ W_attn_in 4MB
__device__ float g_h0[2][B_ * H_];                    // h layer0, [b][k] row-major
__device__ float g_h1[2][B_ * H_];                    // h layer1, [b][k] row-major
__device__ float4 g_cat4[2][(2 * H_ / 4) * B_];       // [slot][h-quad][b] k4 layout
__device__ __nv_bfloat16 g_outs_bf[(size_t)MR_ * H_];
__device__ __nv_bfloat16 g_wlin_bf[(size_t)V_ * D_];
__device__ unsigned g_bar;

__device__ __forceinline__ float sigf(float x) { return 1.f / (1.f + __expf(-x)); }
__device__ __forceinline__ float totf(float x) { return wmma::__float_to_tf32(x); }

__global__ void k_reset() { g_bar = 0u; }

// ---------------- W_lin fp32 -> bf16 ---------------------------------------
__global__ void k_convert_wlin(const float* __restrict__ w) {
    int i = blockIdx.x * blockDim.x + threadIdx.x;
    if (i < (V_ * D_) / 4) {
        float4 v = reinterpret_cast<const float4*>(w)[i];
        __nv_bfloat162* o = reinterpret_cast<__nv_bfloat162*>(g_wlin_bf);
        o[i * 2]     = __floats2bfloat162_rn(v.x, v.y);
        o[i * 2 + 1] = __floats2bfloat162_rn(v.z, v.w);
    }
}

// ---------------- embed + input projection (tf32 WMMA) ----------------------
__global__ void __launch_bounds__(256)
k_gemm_pre(const int* __restrict__ tokens,
           const float* __restrict__ embedding,
           const float* __restrict__ Wih0,
           const float* __restrict__ bih0,
           const float* __restrict__ bhh0) {
    __shared__ float As[128 * 36];
    __shared__ float Bs[128 * 36];
    __shared__ float scr[8 * 320];
    __shared__ float bsh[128];
    __shared__ int   toks[128];
    const int tid = threadIdx.x;
    const int w   = tid >> 5;
    const int lane = tid & 31;
    const int m0 = blockIdx.y * 128, n0 = blockIdx.x * 128;
    const int wm = (w >> 2) * 64, wn = (w & 3) * 32;

    if (tid < 128) {
        int m = m0 + tid;
        toks[tid] = tokens[(m & 31) * T_ + (m >> 5)];
        bsh[tid] = bih0[n0 + tid] + bhh0[n0 + tid];
    }
    __syncthreads();

    wmma::fragment<wmma::accumulator, 16, 16, 8, float> acc[4][2];
#pragma unroll
    for (int i = 0; i < 4; i++)
#pragma unroll
        for (int j = 0; j < 2; j++) wmma::fill_fragment(acc[i][j], 0.f);

    for (int k0 = 0; k0 < D_; k0 += 32) {
#pragma unroll
        for (int it = 0; it < 4; it++) {
            int idx = tid + it * 256;
            int r = idx >> 3, c = (idx & 7) * 4;
            float4 va = *reinterpret_cast<const float4*>(
                embedding + (size_t)toks[r] * D_ + k0 + c);
            As[r * 36 + c] = totf(va.x); As[r * 36 + c + 1] = totf(va.y);
            As[r * 36 + c + 2] = totf(va.z); As[r * 36 + c + 3] = totf(va.w);
            float4 vb = *reinterpret_cast<const float4*>(
                Wih0 + (size_t)(n0 + r) * D_ + k0 + c);
            Bs[r * 36 + c] = totf(vb.x); Bs[r * 36 + c + 1] = totf(vb.y);
            Bs[r * 36 + c + 2] = totf(vb.z); Bs[r * 36 + c + 3] = totf(vb.w);
        }
        __syncthreads();
#pragma unroll
        for (int kk = 0; kk < 4; kk++) {
            wmma::fragment<wmma::matrix_b, 16, 16, 8, wmma::precision::tf32, wmma::col_major> b[2];
#pragma unroll
            for (int j = 0; j < 2; j++)
                wmma::load_matrix_sync(b[j], Bs + (wn + j * 16) * 36 + kk * 8, 36);
#pragma unroll
            for (int i = 0; i < 4; i++) {
                wmma::fragment<wmma::matrix_a, 16, 16, 8, wmma::precision::tf32, wmma::row_major> a;
                wmma::load_matrix_sync(a, As + (wm + i * 16) * 36 + kk * 8, 36);
#pragma unroll
                for (int j = 0; j < 2; j++) wmma::mma_sync(acc[i][j], a, b[j], acc[i][j]);
            }
        }
        __syncthreads();
    }
#pragma unroll
    for (int i = 0; i < 4; i++)
#pragma unroll
        for (int j = 0; j < 2; j++) {
            wmma::store_matrix_sync(scr + w * 320, acc[i][j], 20, wmma::mem_row_major);
            __syncwarp();
            int c = lane >> 1;
            int r0 = (lane & 1) * 8;
            int n = n0 + wn + j * 16 + c;
            int mbase = m0 + wm + i * 16 + r0;
            int t = mbase >> 5, b0 = mbase & 31;
            float bias = bsh[wn + j * 16 + c];
            float* dst = g_pre0 + ((size_t)t * G4_ + n) * B_ + b0;
#pragma unroll
            for (int rr = 0; rr < 8; rr++)
                dst[rr] = scr[w * 320 + (r0 + rr) * 20 + c] + bias;
            __syncwarp();
        }
}

// ---------------- C2 = context @ W_attn_in (tf32 WMMA) ----------------------
__global__ void __launch_bounds__(256)
k_c2(const float* __restrict__ A, const float* __restrict__ Wq) {
    __shared__ float As[128 * 36];
    __shared__ float Bs[32 * 132];
    const int tid = threadIdx.x;
    const int w   = tid >> 5;
    const int m0 = blockIdx.y * 128, n0 = blockIdx.x * 128;
    const int wm = (w >> 2) * 64, wn = (w & 3) * 32;

    wmma::fragment<wmma::accumulator, 16, 16, 8, float> acc[4][2];
#pragma unroll
    for (int i = 0; i < 4; i++)
#pragma unroll
        for (int j = 0; j < 2; j++) wmma::fill_fragment(acc[i][j], 0.f);

    for (int k0 = 0; k0 < H_; k0 += 32) {
#pragma unroll
        for (int it = 0; it < 4; it++) {
            int idx = tid + it * 256;
            int r = idx >> 3, c = (idx & 7) * 4;
            float4 va = *reinterpret_cast<const float4*>(
                A + (size_t)(m0 + r) * H_ + k0 + c);
            As[r * 36 + c] = totf(va.x); As[r * 36 + c + 1] = totf(va.y);
            As[r * 36 + c + 2] = totf(va.z); As[r * 36 + c + 3] = totf(va.w);
        }
#pragma unroll
        for (int it = 0; it < 4; it++) {
            int idx = tid + it * 256;
            int r = idx >> 5, c = (idx & 31) * 4;
            float4 vb = *reinterpret_cast<const float4*>(
                Wq + (size_t)(k0 + r) * H_ + n0 + c);
            Bs[r * 132 + c] = totf(vb.x); Bs[r * 132 + c + 1] = totf(vb.y);
            Bs[r * 132 + c + 2] = totf(vb.z); Bs[r * 132 + c + 3] = totf(vb.w);
        }
        __syncthreads();
#pragma unroll
        for (int kk = 0; kk < 4; kk++) {
            wmma::fragment<wmma::matrix_b, 16, 16, 8, wmma::precision::tf32, wmma::row_major> b[2];
#pragma unroll
            for (int j = 0; j < 2; j++)
                wmma::load_matrix_sync(b[j], Bs + kk * 8 * 132 + wn + j * 16, 132);
#pragma unroll
            for (int i = 0; i < 4; i++) {
                wmma::fragment<wmma::matrix_a, 16, 16, 8, wmma::precision::tf32, wmma::row_major> a;
                wmma::load_matrix_sync(a, As + (wm + i * 16) * 36 + kk * 8, 36);
#pragma unroll
                for (int j = 0; j < 2; j++) wmma::mma_sync(acc[i][j], a, b[j], acc[i][j]);
            }
        }
        __syncthreads();
    }
#pragma unroll
    for (int i = 0; i < 4; i++)
#pragma unroll
        for (int j = 0; j < 2; j++)
            wmma::store_matrix_sync(g_c2 + (size_t)(m0 + wm + i * 16) * H_ + n0 + wn + j * 16,
                                    acc[i][j], H_, wmma::mem_row_major);
}

// ---------------- pipelined persistent scan kernel ---------------------------
// SMEM float offsets
#define SM_W0    0                          // 16 x 520
#define SM_W1    8320                       // 16 x 1040
#define SM_WOS   24960                      // 4 x 1024
#define SM_STAGE 29056                      // 32 x 520
#define SM_PBUF0 45696                      // 8 x 256
#define SM_PBUF1 47744                      // 8 x 256
#define SM_GBUF0 49792                      // 16 x 32
#define SM_GBUF1 50304                      // 16 x 32
#define SM_CB    50816                      // 2 x 4 x 32
#define SM_B1    51072                      // 16
#define SM_PART  51088                      // 8 x 32
#define SM_SC    51344                      // 64
#define SM_ATT   51408                      // 64
#define SMEM_FLOATS 51472
#define SMEM_BYTES  (SMEM_FLOATS * 4)

#define LDW0  520
#define LDW1  1040
#define LDST  520

__device__ __forceinline__ void gridbar(unsigned target) {
    __threadfence();
    __syncthreads();
    if (threadIdx.x == 0) {
        atomicAdd(&g_bar, 1u);
        volatile unsigned* vb = &g_bar;
        while (*vb < target) __nanosleep(32);
    }
    __syncthreads();
}

// copy 32x512 row-major h into padded stage [b][520], rounding to tf32
__device__ __forceinline__ void stage_rows(float* stg, const float4* src, int tid) {
    for (int idx = tid; idx < 4096; idx += 256) {
        int b = idx >> 7, j = idx & 127;
        float4 v = __ldcg(&src[idx]);
        v.x = totf(v.x); v.y = totf(v.y); v.z = totf(v.z); v.w = totf(v.w);
        reinterpret_cast<float4*>(stg + b * LDST)[j] = v;
    }
}

__global__ void __launch_bounds__(256, 1)
k_scan(const float* __restrict__ Whh0, const float* __restrict__ Wih1,
       const float* __restrict__ Whh1, const float* __restrict__ bih,
       const float* __restrict__ bhh, const float* __restrict__ context,
       const float* __restrict__ Wout, const float* __restrict__ h0in,
       const float* __restrict__ c0in, float* __restrict__ out) {
    extern __shared__ float sm[];
    float*  W0s   = sm + SM_W0;
    float*  W1s   = sm + SM_W1;
    float*  Wos   = sm + SM_WOS;
    float*  stg   = sm + SM_STAGE;
    float*  pbuf0 = sm + SM_PBUF0;
    float*  pbuf1 = sm + SM_PBUF1;
    float*  gbuf0 = sm + SM_GBUF0;
    float*  gbuf1 = sm + SM_GBUF1;
    float*  cb    = sm + SM_CB;
    float*  bias1 = sm + SM_B1;
    float*  part  = sm + SM_PART;
    float*  sc    = sm + SM_SC;
    float*  att   = sm + SM_ATT;

    const int cta = blockIdx.x;
    const int tid = threadIdx.x;
    const int w   = tid >> 5;
    const int lane = tid & 31;
    const int u0  = cta * UPC_;
    const int wn  = w & 1;            // n-tile (batch 16s)
    const int wkc = w >> 1;           // k-chunk (128s)
    const int ab  = cta & 31;         // attention batch
    const int aq  = cta >> 5;         // attention quarter (0..3)

    // -------- prologue: weights -> SMEM (pre-rounded to tf32) --------------
    for (int idx = tid; idx < 16 * 128; idx += 256) {
        int r = idx >> 7, kq = idx & 127;
        int row = ((r >> 2) * H_) + u0 + (r & 3);
        float4 v = *reinterpret_cast<const float4*>(Whh0 + (size_t)row * H_ + kq * 4);
        v.x = totf(v.x); v.y = totf(v.y); v.z = totf(v.z); v.w = totf(v.w);
        reinterpret_cast<float4*>(W0s + r * LDW0)[kq] = v;
    }
    for (int idx = tid; idx < 16 * 256; idx += 256) {
        int r = idx >> 8, kq = idx & 255;
        int row = ((r >> 2) * H_) + u0 + (r & 3);
        const float* src = (kq < 128)
            ? (Wih1 + (size_t)row * H_ + kq * 4)
            : (Whh1 + (size_t)row * H_ + (kq - 128) * 4);
        float4 v = *reinterpret_cast<const float4*>(src);
        v.x = totf(v.x); v.y = totf(v.y); v.z = totf(v.z); v.w = totf(v.w);
        reinterpret_cast<float4*>(W1s + r * LDW1)[kq] = v;
    }
    for (int idx = tid; idx < 4 * 256; idx += 256) {     // Wos fp32
        int r = idx >> 8, kq = idx & 255;
        reinterpret_cast<float4*>(Wos + r * 1024)[kq] =
            *reinterpret_cast<const float4*>(Wout + (size_t)(u0 + r) * (2 * H_) + kq * 4);
    }
    if (tid < 16) {
        int row = ((tid >> 2) * H_) + u0 + (tid & 3);
        bias1[tid] = bih[G4_ + row] + bhh[G4_ + row];
    }
    {   // cell state: cb[l*128 + ul*32 + b]
        int l = tid >> 7, ul = (tid >> 5) & 3, b = tid & 31;
        cb[tid] = c0in[(size_t)l * B_ * H_ + (size_t)b * H_ + u0 + ul];
    }
    if (tid < 32) {   // initial h -> slot 1 (read at tick 0 / tick 1)
        int b = tid;
#pragma unroll
        for (int ul = 0; ul < 4; ul++) {
            __stcg(&g_h0[1][b * H_ + u0 + ul], h0in[(size_t)b * H_ + u0 + ul]);
            __stcg(&g_h1[1][b * H_ + u0 + ul], h0in[(size_t)B_ * H_ + b * H_ + u0 + ul]);
        }
    }
    unsigned nbar = 0;
    gridbar(++nbar * CTAS_);

    // -------- pipelined main loop: tick tau computes
    //          L0(t=tau), L1(t=tau-1), attn(t=tau-2), attnout(t=tau-3) -------
    for (int tau = 0; tau < NT_; tau++) {
        const int sh0r = (tau + 1) & 1, sh0w = tau & 1;
        const int sh1r = tau & 1,       sh1w = (tau + 1) & 1;
        const int catw = tau & 1,       catr = (tau + 1) & 1;

        // (a) stage h0out_{tau-1} (shared B operand of L0 and L1-pass0)
        stage_rows(stg, reinterpret_cast<const float4*>(g_h0[sh0r]), tid);
        __syncthreads();

        // (b) L0 mma (acc0) + L1 pass0 mma (acc1) off the same stage
        wmma::fragment<wmma::accumulator, 16, 16, 8, float> acc0, acc1;
        wmma::fill_fragment(acc0, 0.f);
        wmma::fill_fragment(acc1, 0.f);
#pragma unroll
        for (int kk = 0; kk < 16; kk++) {
            int k = wkc * 128 + kk * 8;
            wmma::fragment<wmma::matrix_b, 16, 16, 8, wmma::precision::tf32, wmma::col_major> b;
            wmma::load_matrix_sync(b, stg + (wn * 16) * LDST + k, LDST);
            wmma::fragment<wmma::matrix_a, 16, 16, 8, wmma::precision::tf32, wmma::row_major> a0, a1;
            wmma::load_matrix_sync(a0, W0s + k, LDW0);
            wmma::load_matrix_sync(a1, W1s + k, LDW1);
            wmma::mma_sync(acc0, a0, b, acc0);
            wmma::mma_sync(acc1, a1, b, acc1);
        }
        __syncthreads();   // done reading stage

        // (c) restage with h1out_{tau-2} (L1 pass1 B operand + attn q rows)
        stage_rows(stg, reinterpret_cast<const float4*>(g_h1[sh1r]), tid);
        __syncthreads();

        // (d) L1 pass1 mma
#pragma unroll
        for (int kk = 0; kk < 16; kk++) {
            int k = wkc * 128 + kk * 8;
            wmma::fragment<wmma::matrix_b, 16, 16, 8, wmma::precision::tf32, wmma::col_major> b;
            wmma::load_matrix_sync(b, stg + (wn * 16) * LDST + k, LDST);
            wmma::fragment<wmma::matrix_a, 16, 16, 8, wmma::precision::tf32, wmma::row_major> a;
            wmma::load_matrix_sync(a, W1s + 512 + k, LDW1);
            wmma::mma_sync(acc1, a, b, acc1);
        }
        wmma::store_matrix_sync(pbuf0 + w * 256, acc0, 16, wmma::mem_row_major);
        wmma::store_matrix_sync(pbuf1 + w * 256, acc1, 16, wmma::mem_row_major);
        __syncthreads();

        // (e) k-chunk reductions
        if (tau <= 63)
            for (int o = tid; o < 512; o += 256) {
                int r = o >> 5, b = o & 31;
                float s = 0.f;
#pragma unroll
                for (int kc = 0; kc < 4; kc++)
                    s += pbuf0[((b >> 4) + 2 * kc) * 256 + r * 16 + (b & 15)];
                gbuf0[r * 32 + b] = s;
            }
        if (tau >= 1 && tau <= 64)
            for (int o = tid; o < 512; o += 256) {
                int r = o >> 5, b = o & 31;
                float s = 0.f;
#pragma unroll
                for (int kc = 0; kc < 4; kc++)
                    s += pbuf1[((b >> 4) + 2 * kc) * 256 + r * 16 + (b & 15)];
                gbuf1[r * 32 + b] = s;
            }
        __syncthreads();

        // (f) L0 epilogue on warps 0-3, L1 epilogue on warps 4-7 (parallel)
        if (tau <= 63 && tid < 128) {
            int t = tau;
            int ul = tid >> 5, b = tid & 31, u = u0 + ul;
            const float* pre = g_pre0 + (size_t)t * G4_ * B_;
            float gi = sigf(gbuf0[(0  + ul) * 32 + b] + __ldg(&pre[((size_t)0 * H_ + u) * B_ + b]));
            float gf = sigf(gbuf0[(4  + ul) * 32 + b] + __ldg(&pre[((size_t)1 * H_ + u) * B_ + b]));
            float gg = tanhf(gbuf0[(8  + ul) * 32 + b] + __ldg(&pre[((size_t)2 * H_ + u) * B_ + b]));
            float go = sigf(gbuf0[(12 + ul) * 32 + b] + __ldg(&pre[((size_t)3 * H_ + u) * B_ + b]));
            float c = gf * cb[ul * 32 + b] + gi * gg;
            cb[ul * 32 + b] = c;
            float h = go * tanhf(c);
            __stcg(&g_h0[sh0w][b * H_ + u], h);
            if (t == T_ - 1) {
                out[OFF_HT + (size_t)b * H_ + u] = h;
                out[OFF_CT + (size_t)b * H_ + u] = c;
            }
        }
        if (tau >= 1 && tau <= 64 && tid >= 128) {
            int t = tau - 1;
            int tt = tid - 128;
            int ul = tt >> 5, b = tt & 31, u = u0 + ul;
            float gi = sigf(gbuf1[(0  + ul) * 32 + b] + bias1[0  + ul]);
            float gf = sigf(gbuf1[(4  + ul) * 32 + b] + bias1[4  + ul]);
            float gg = tanhf(gbuf1[(8  + ul) * 32 + b] + bias1[8  + ul]);
            float go = sigf(gbuf1[(12 + ul) * 32 + b] + bias1[12 + ul]);
            float c = gf * cb[128 + ul * 32 + b] + gi * gg;
            cb[128 + ul * 32 + b] = c;
            float h = go * tanhf(c);
            __stcg(&g_h1[sh1w][b * H_ + u], h);
            if (t == T_ - 1) {
                out[OFF_HT + (size_t)B_ * H_ + (size_t)b * H_ + u] = h;
                out[OFF_CT + (size_t)B_ * H_ + (size_t)b * H_ + u] = c;
            }
        }

        // (g) attention for t = tau-2 (stg still holds h1out_{tau-2})
        if (tau >= 2 && tau <= 65) {
            const float4* qs4 = reinterpret_cast<const float4*>(stg + ab * LDST);
#pragma unroll
            for (int si = 0; si < 8; si++) {
                int s = w * 8 + si;
                const float4* c2r = reinterpret_cast<const float4*>(
                    g_c2 + (size_t)(ab * S_ + s) * H_);
                float a = 0.f;
#pragma unroll
                for (int kq = lane; kq < 128; kq += 32) {
                    float4 cv = __ldg(&c2r[kq]);
                    float4 qv = qs4[kq];
                    a += cv.x * qv.x + cv.y * qv.y + cv.z * qv.z + cv.w * qv.w;
                }
#pragma unroll
                for (int off = 16; off; off >>= 1) a += __shfl_xor_sync(0xffffffffu, a, off);
                if (lane == 0) sc[s] = a;
            }
            __syncthreads();
            if (tid < 32) {
                float v0 = sc[tid], v1 = sc[tid + 32];
                float m = fmaxf(v0, v1);
#pragma unroll
                for (int off = 16; off; off >>= 1) m = fmaxf(m, __shfl_xor_sync(0xffffffffu, m, off));
                float e0 = __expf(v0 - m), e1 = __expf(v1 - m);
                float s2 = e0 + e1;
#pragma unroll
                for (int off = 16; off; off >>= 1) s2 += __shfl_xor_sync(0xffffffffu, s2, off);
                float inv = 1.f / s2;
                att[tid] = e0 * inv; att[tid + 32] = e1 * inv;
                if (aq == 0 && tau == 65) {
                    out[OFF_ATTN + ab * S_ + tid]      = e0 * inv;
                    out[OFF_ATTN + ab * S_ + tid + 32] = e1 * inv;
                }
            }
            __syncthreads();
            {   // ctx: quarter handles h in [aq*128, aq*128+128); 2 threads per h
                int h = aq * 128 + (tid >> 1);
                int s0 = (tid & 1) * 32;
                const float* cx = context + (size_t)ab * S_ * H_ + h;
                float a = 0.f;
#pragma unroll 8
                for (int s = s0; s < s0 + 32; s++) a += att[s] * cx[(size_t)s * H_];
                a += __shfl_xor_sync(0xffffffffu, a, 1);
                if ((tid & 1) == 0) {
                    float* catp = reinterpret_cast<float*>(g_cat4[catw]);
                    __stcg(&catp[((h >> 2) * 32 + ab) * 4 + (h & 3)], a);
                    int h2 = H_ + h;
                    float hv = __ldcg(&g_h1[sh1r][ab * H_ + h]);
                    __stcg(&catp[((h2 >> 2) * 32 + ab) * 4 + (h2 & 3)], hv);
                }
            }
        }

        // (h) attention-out for t = tau-3 (reads cat4 prev slot via L2)
        if (tau >= 3) {
            const int tO = tau - 3;
            float oa = 0.f, ob = 0.f;
            const int row = w & 3, sub = w >> 2;
            const int i0 = sub * 64;
#pragma unroll
            for (int half = 0; half < 2; half++) {
                const float4* wr = reinterpret_cast<const float4*>(Wos + row * 1024 + half * H_);
                const float4* catp = g_cat4[catr] + half * 4096;
#pragma unroll 4
                for (int i = 0; i < 64; i++) {
                    float4 h = __ldcg(&catp[(i0 + i) * 32 + lane]);
                    float4 x = wr[i0 + i];
                    oa += x.x * h.x + x.y * h.y;
                    ob += x.z * h.z + x.w * h.w;
                }
            }
            part[w * 32 + lane] = oa + ob;
            __syncthreads();
            if (tid < 128) {
                int r = tid >> 5, b = tid & 31;
                float v = tanhf(part[r * 32 + b] + part[(r + 4) * 32 + b]);
                g_outs_bf[((size_t)tO * B_ + b) * H_ + u0 + r] = __float2bfloat16(v);
            }
        }

        if (tau != NT_ - 1) gridbar(++nbar * CTAS_);
    }
}

// ---------------- vocab GEMM: logits = outs_bf @ wlin_bf^T ------------------
__global__ void __launch_bounds__(256)
k_wmma(float* __restrict__ C) {
    __shared__ __align__(16) __nv_bfloat16 As[2][128 * 40];
    __shared__ __align__(16) __nv_bfloat16 Bs[2][128 * 40];
    const int m0 = blockIdx.y * 128, n0 = blockIdx.x * 128;
    const int tid = threadIdx.x;
    const int wid = tid >> 5;
    const int wm = (wid >> 2) * 64, wn = (wid & 3) * 32;
    wmma::fragment<wmma::accumulator, 16, 16, 16, float> acc[4][2];
#pragma unroll
    for (int i = 0; i < 4; i++)
#pragma unroll
        for (int j = 0; j < 2; j++) wmma::fill_fragment(acc[i][j], 0.f);
    const int r = tid >> 1;
    const int c = (tid & 1) * 16;

#pragma unroll
    for (int q = 0; q < 2; q++) {
        *reinterpret_cast<uint4*>(&As[0][r * 40 + c + q * 8]) =
            *reinterpret_cast<const uint4*>(&g_outs_bf[(size_t)(m0 + r) * D_ + c + q * 8]);
        *reinterpret_cast<uint4*>(&Bs[0][r * 40 + c + q * 8]) =
            *reinterpret_cast<const uint4*>(&g_wlin_bf[(size_t)(n0 + r) * D_ + c + q * 8]);
    }
    __syncthreads();

    int buf = 0;
    for (int k0 = 0; k0 < D_; k0 += 32) {
        uint4 ra[2], rb[2];
        const bool has_next = (k0 + 32 < D_);
        if (has_next) {
#pragma unroll
            for (int q = 0; q < 2; q++) {
                ra[q] = *reinterpret_cast<const uint4*>(
                    &g_outs_bf[(size_t)(m0 + r) * D_ + k0 + 32 + c + q * 8]);
                rb[q] = *reinterpret_cast<const uint4*>(
                    &g_wlin_bf[(size_t)(n0 + r) * D_ + k0 + 32 + c + q * 8]);
            }
        }
#pragma unroll
        for (int sub = 0; sub < 2; sub++) {
            wmma::fragment<wmma::matrix_b, 16, 16, 16, __nv_bfloat16, wmma::col_major> bf[2];
#pragma unroll
            for (int j = 0; j < 2; j++)
                wmma::load_matrix_sync(bf[j], &Bs[buf][(wn + j * 16) * 40 + sub * 16], 40);
#pragma unroll
            for (int i = 0; i < 4; i++) {
                wmma::fragment<wmma::matrix_a, 16, 16, 16, __nv_bfloat16, wmma::row_major> af;
                wmma::load_matrix_sync(af, &As[buf][(wm + i * 16) * 40 + sub * 16], 40);
#pragma unroll
                for (int j = 0; j < 2; j++) wmma::mma_sync(acc[i][j], af, bf[j], acc[i][j]);
            }
        }
        if (has_next) {
#pragma unroll
            for (int q = 0; q < 2; q++) {
                *reinterpret_cast<uint4*>(&As[buf ^ 1][r * 40 + c + q * 8]) = ra[q];
                *reinterpret_cast<uint4*>(&Bs[buf ^ 1][r * 40 + c + q * 8]) = rb[q];
            }
        }
        __syncthreads();
        buf ^= 1;
    }
#pragma unroll
    for (int i = 0; i < 4; i++)
#pragma unroll
        for (int j = 0; j < 2; j++)
            wmma::store_matrix_sync(C + (size_t)(m0 + wm + i * 16) * V_ + n0 + wn + j * 16,
                                    acc[i][j], V_, wmma::mem_row_major);
}

// ---------------- log_softmax (adds b_lin, in-place, float4 vectorized) -----
__global__ void k_logsoftmax(float* __restrict__ logits, const float* __restrict__ b_lin) {
    const int row = blockIdx.x;
    float* p = logits + (size_t)row * V_;
    float4* p4 = reinterpret_cast<float4*>(p);
    const float4* b4 = reinterpret_cast<const float4*>(b_lin);
    const int tid = threadIdx.x;
    float m = -1e30f, s = 0.f;
    for (int v = tid; v < V_ / 4; v += 256) {
        float4 x = p4[v], bb = b4[v];
        float e[4] = {x.x + bb.x, x.y + bb.y, x.z + bb.z, x.w + bb.w};
#pragma unroll
        for (int q = 0; q < 4; q++) {
            if (e[q] > m) { s = s * __expf(m - e[q]) + 1.f; m = e[q]; }
            else          { s += __expf(e[q] - m); }
        }
    }
    __shared__ float sm[256], ss[256];
    sm[tid] = m; ss[tid] = s;
    __syncthreads();
    for (int off = 128; off; off >>= 1) {
        if (tid < off) {
            float m2 = sm[tid + off], s2 = ss[tid + off];
            float M = fmaxf(sm[tid], m2);
            ss[tid] = ss[tid] * __expf(sm[tid] - M) + s2 * __expf(m2 - M);
            sm[tid] = M;
        }
        __syncthreads();
    }
    float lse = sm[0] + logf(ss[0]);
    for (int v = tid; v < V_ / 4; v += 256) {
        float4 x = p4[v], bb = b4[v];
        x.x = x.x + bb.x - lse; x.y = x.y + bb.y - lse;
        x.z = x.z + bb.z - lse; x.w = x.w + bb.w - lse;
        p4[v] = x;
    }
}

// ---------------- host driver ----------------------------------------------
extern "C" void kernel_launch(void* const* d_in, const int* in_sizes, int n_in,
                              void* d_out, int out_size) {
    const int*   tokens     = (const int*)d_in[0];
    const float* h0         = (const float*)d_in[1];
    const float* c0         = (const float*)d_in[2];
    const float* context    = (const float*)d_in[3];
    const float* embedding  = (const float*)d_in[4];
    const float* Wih        = (const float*)d_in[5];
    const float* Whh        = (const float*)d_in[6];
    const float* bih        = (const float*)d_in[7];
    const float* bhh        = (const float*)d_in[8];
    const float* W_attn_in  = (const float*)d_in[9];
    const float* W_attn_out = (const float*)d_in[10];
    const float* W_lin      = (const float*)d_in[11];
    const float* b_lin      = (const float*)d_in[12];
    float* out = (float*)d_out;

    cudaFuncSetAttribute(k_scan, cudaFuncAttributeMaxDynamicSharedMemorySize, SMEM_BYTES);

    const float* Wih1 = Wih + (size_t)G4_ * D_;
    const float* Whh1 = Whh + (size_t)G4_ * H_;

    k_reset<<<1, 1>>>();
    k_convert_wlin<<<(V_ * D_ / 4 + 255) / 256, 256>>>(W_lin);
    k_gemm_pre<<<dim3(G4_ / 128, MR_ / 128), 256>>>(tokens, embedding, Wih, bih, bhh);
    k_c2<<<dim3(H_ / 128, (B_ * S_) / 128), 256>>>(context, W_attn_in);
    k_scan<<<CTAS_, 256, SMEM_BYTES>>>(Whh, Wih1, Whh1, bih, bhh, context,
                                       W_attn_out, h0, c0, out);
    k_wmma<<<dim3(V_ / 128, MR_ / 128), 256>>>(out);
    k_logsoftmax<<<MR_, 256>>>(out, b_lin);
}

// round 12
// speedup vs baseline: 1.3101x; 1.2374x over previous
#include <cuda_runtime.h>
#include <cuda_bf16.h>
#include <mma.h>
using namespace nvcuda;

#define B_  32
#define T_  64
#define S_  64
#define H_  512
#define D_  512
#define V_  32000
#define G4_ 2048            // 4*H
#define MR_ 2048            // T*B rows

#define CTAS_ 128
#define UPC_  4             // units per CTA (both layers)
#define NT_   67            // pipelined ticks = T + 3

// d_out layout (f32): log_probs [T,B,V], hT [2,B,H], cT [2,B,H], attn [B,S]
#define OFF_HT   ((size_t)T_ * B_ * V_)
#define OFF_CT   (OFF_HT + (size_t)2 * B_ * H_)
#define OFF_ATTN (OFF_CT + (size_t)2 * B_ * H_)

// ---------------- device scratch -------------------------------------------
__device__ float g_pre0[(size_t)T_ * G4_ * B_];       // [t][gate_row][b]  16MB
__device__ float g_c2[(size_t)B_ * S_ * H_];          // context @ W_attn_in 4MB
__device__ float g_h0[2][B_ * H_];                    // h layer0, [b][k] row-major
__device__ float g_h1[2][B_ * H_];                    // h layer1, [b][k] row-major
__device__ float4 g_cat4[2][(2 * H_ / 4) * B_];       // [slot][h-quad][b] k4 layout
__device__ __nv_bfloat16 g_outs_bf[(size_t)MR_ * H_];
__device__ __nv_bfloat16 g_wlin_bf[(size_t)V_ * D_];
__device__ unsigned g_bar;

__device__ __forceinline__ float sigf(float x) { return 1.f / (1.f + __expf(-x)); }
__device__ __forceinline__ float totf(float x) { return wmma::__float_to_tf32(x); }

__global__ void k_reset() { g_bar = 0u; }

// ---------------- W_lin fp32 -> bf16 ---------------------------------------
__global__ void k_convert_wlin(const float* __restrict__ w) {
    int i = blockIdx.x * blockDim.x + threadIdx.x;
    if (i < (V_ * D_) / 4) {
        float4 v = reinterpret_cast<const float4*>(w)[i];
        __nv_bfloat162* o = reinterpret_cast<__nv_bfloat162*>(g_wlin_bf);
        o[i * 2]     = __floats2bfloat162_rn(v.x, v.y);
        o[i * 2 + 1] = __floats2bfloat162_rn(v.z, v.w);
    }
}

// ---------------- embed + input projection (tf32 WMMA) ----------------------
__global__ void __launch_bounds__(256)
k_gemm_pre(const int* __restrict__ tokens,
           const float* __restrict__ embedding,
           const float* __restrict__ Wih0,
           const float* __restrict__ bih0,
           const float* __restrict__ bhh0) {
    __shared__ float As[128 * 36];
    __shared__ float Bs[128 * 36];
    __shared__ float scr[8 * 320];
    __shared__ float bsh[128];
    __shared__ int   toks[128];
    const int tid = threadIdx.x;
    const int w   = tid >> 5;
    const int lane = tid & 31;
    const int m0 = blockIdx.y * 128, n0 = blockIdx.x * 128;
    const int wm = (w >> 2) * 64, wn = (w & 3) * 32;

    if (tid < 128) {
        int m = m0 + tid;
        toks[tid] = tokens[(m & 31) * T_ + (m >> 5)];
        bsh[tid] = bih0[n0 + tid] + bhh0[n0 + tid];
    }
    __syncthreads();

    wmma::fragment<wmma::accumulator, 16, 16, 8, float> acc[4][2];
#pragma unroll
    for (int i = 0; i < 4; i++)
#pragma unroll
        for (int j = 0; j < 2; j++) wmma::fill_fragment(acc[i][j], 0.f);

    for (int k0 = 0; k0 < D_; k0 += 32) {
#pragma unroll
        for (int it = 0; it < 4; it++) {
            int idx = tid + it * 256;
            int r = idx >> 3, c = (idx & 7) * 4;
            float4 va = *reinterpret_cast<const float4*>(
                embedding + (size_t)toks[r] * D_ + k0 + c);
            As[r * 36 + c] = totf(va.x); As[r * 36 + c + 1] = totf(va.y);
            As[r * 36 + c + 2] = totf(va.z); As[r * 36 + c + 3] = totf(va.w);
            float4 vb = *reinterpret_cast<const float4*>(
                Wih0 + (size_t)(n0 + r) * D_ + k0 + c);
            Bs[r * 36 + c] = totf(vb.x); Bs[r * 36 + c + 1] = totf(vb.y);
            Bs[r * 36 + c + 2] = totf(vb.z); Bs[r * 36 + c + 3] = totf(vb.w);
        }
        __syncthreads();
#pragma unroll
        for (int kk = 0; kk < 4; kk++) {
            wmma::fragment<wmma::matrix_b, 16, 16, 8, wmma::precision::tf32, wmma::col_major> b[2];
#pragma unroll
            for (int j = 0; j < 2; j++)
                wmma::load_matrix_sync(b[j], Bs + (wn + j * 16) * 36 + kk * 8, 36);
#pragma unroll
            for (int i = 0; i < 4; i++) {
                wmma::fragment<wmma::matrix_a, 16, 16, 8, wmma::precision::tf32, wmma::row_major> a;
                wmma::load_matrix_sync(a, As + (wm + i * 16) * 36 + kk * 8, 36);
#pragma unroll
                for (int j = 0; j < 2; j++) wmma::mma_sync(acc[i][j], a, b[j], acc[i][j]);
            }
        }
        __syncthreads();
    }
#pragma unroll
    for (int i = 0; i < 4; i++)
#pragma unroll
        for (int j = 0; j < 2; j++) {
            wmma::store_matrix_sync(scr + w * 320, acc[i][j], 20, wmma::mem_row_major);
            __syncwarp();
            int c = lane >> 1;
            int r0 = (lane & 1) * 8;
            int n = n0 + wn + j * 16 + c;
            int mbase = m0 + wm + i * 16 + r0;
            int t = mbase >> 5, b0 = mbase & 31;
            float bias = bsh[wn + j * 16 + c];
            float* dst = g_pre0 + ((size_t)t * G4_ + n) * B_ + b0;
#pragma unroll
            for (int rr = 0; rr < 8; rr++)
                dst[rr] = scr[w * 320 + (r0 + rr) * 20 + c] + bias;
            __syncwarp();
        }
}

// ---------------- C2 = context @ W_attn_in (tf32 WMMA) ----------------------
__global__ void __launch_bounds__(256)
k_c2(const float* __restrict__ A, const float* __restrict__ Wq) {
    __shared__ float As[128 * 36];
    __shared__ float Bs[32 * 132];
    const int tid = threadIdx.x;
    const int w   = tid >> 5;
    const int m0 = blockIdx.y * 128, n0 = blockIdx.x * 128;
    const int wm = (w >> 2) * 64, wn = (w & 3) * 32;

    wmma::fragment<wmma::accumulator, 16, 16, 8, float> acc[4][2];
#pragma unroll
    for (int i = 0; i < 4; i++)
#pragma unroll
        for (int j = 0; j < 2; j++) wmma::fill_fragment(acc[i][j], 0.f);

    for (int k0 = 0; k0 < H_; k0 += 32) {
#pragma unroll
        for (int it = 0; it < 4; it++) {
            int idx = tid + it * 256;
            int r = idx >> 3, c = (idx & 7) * 4;
            float4 va = *reinterpret_cast<const float4*>(
                A + (size_t)(m0 + r) * H_ + k0 + c);
            As[r * 36 + c] = totf(va.x); As[r * 36 + c + 1] = totf(va.y);
            As[r * 36 + c + 2] = totf(va.z); As[r * 36 + c + 3] = totf(va.w);
        }
#pragma unroll
        for (int it = 0; it < 4; it++) {
            int idx = tid + it * 256;
            int r = idx >> 5, c = (idx & 31) * 4;
            float4 vb = *reinterpret_cast<const float4*>(
                Wq + (size_t)(k0 + r) * H_ + n0 + c);
            Bs[r * 132 + c] = totf(vb.x); Bs[r * 132 + c + 1] = totf(vb.y);
            Bs[r * 132 + c + 2] = totf(vb.z); Bs[r * 132 + c + 3] = totf(vb.w);
        }
        __syncthreads();
#pragma unroll
        for (int kk = 0; kk < 4; kk++) {
            wmma::fragment<wmma::matrix_b, 16, 16, 8, wmma::precision::tf32, wmma::row_major> b[2];
#pragma unroll
            for (int j = 0; j < 2; j++)
                wmma::load_matrix_sync(b[j], Bs + kk * 8 * 132 + wn + j * 16, 132);
#pragma unroll
            for (int i = 0; i < 4; i++) {
                wmma::fragment<wmma::matrix_a, 16, 16, 8, wmma::precision::tf32, wmma::row_major> a;
                wmma::load_matrix_sync(a, As + (wm + i * 16) * 36 + kk * 8, 36);
#pragma unroll
                for (int j = 0; j < 2; j++) wmma::mma_sync(acc[i][j], a, b[j], acc[i][j]);
            }
        }
        __syncthreads();
    }
#pragma unroll
    for (int i = 0; i < 4; i++)
#pragma unroll
        for (int j = 0; j < 2; j++)
            wmma::store_matrix_sync(g_c2 + (size_t)(m0 + wm + i * 16) * H_ + n0 + wn + j * 16,
                                    acc[i][j], H_, wmma::mem_row_major);
}

// ---------------- pipelined persistent scan kernel ---------------------------
// SMEM float offsets
#define SM_W0    0                          // 16 x 520
#define SM_W1    8320                       // 16 x 1040
#define SM_WOS   24960                      // 4 x 1024
#define SM_STAGE 29056                      // 32 x 520
#define SM_PBUF0 45696                      // 8 x 256
#define SM_PBUF1 47744                      // 8 x 256
#define SM_GBUF0 49792                      // 16 x 32
#define SM_GBUF1 50304                      // 16 x 32
#define SM_CB    50816                      // 2 x 4 x 32
#define SM_B1    51072                      // 16
#define SM_PART  51088                      // 4 x 8 x 32 = 1024
#define SM_SC    52112                      // 64
#define SM_ATT   52176                      // 64
#define SMEM_FLOATS 52240
#define SMEM_BYTES  (SMEM_FLOATS * 4)

#define LDW0  520
#define LDW1  1040
#define LDST  520

__device__ __forceinline__ void gridbar(unsigned target) {
    __threadfence();
    __syncthreads();
    if (threadIdx.x == 0) {
        atomicAdd(&g_bar, 1u);
        volatile unsigned* vb = &g_bar;
        while (*vb < target) __nanosleep(32);
    }
    __syncthreads();
}

// copy 32x512 row-major h into padded stage [b][520], rounding to tf32
__device__ __forceinline__ void stage_rows(float* stg, const float4* src, int tid) {
    for (int idx = tid; idx < 4096; idx += 256) {
        int b = idx >> 7, j = idx & 127;
        float4 v = __ldcg(&src[idx]);
        v.x = totf(v.x); v.y = totf(v.y); v.z = totf(v.z); v.w = totf(v.w);
        reinterpret_cast<float4*>(stg + b * LDST)[j] = v;
    }
}

__global__ void __launch_bounds__(256, 1)
k_scan(const float* __restrict__ Whh0, const float* __restrict__ Wih1,
       const float* __restrict__ Whh1, const float* __restrict__ bih,
       const float* __restrict__ bhh, const float* __restrict__ context,
       const float* __restrict__ Wout, const float* __restrict__ h0in,
       const float* __restrict__ c0in, float* __restrict__ out) {
    extern __shared__ float sm[];
    float*  W0s   = sm + SM_W0;
    float*  W1s   = sm + SM_W1;
    float*  Wos   = sm + SM_WOS;
    float*  stg   = sm + SM_STAGE;
    float*  pbuf0 = sm + SM_PBUF0;
    float*  pbuf1 = sm + SM_PBUF1;
    float*  gbuf0 = sm + SM_GBUF0;
    float*  gbuf1 = sm + SM_GBUF1;
    float*  cb    = sm + SM_CB;
    float*  bias1 = sm + SM_B1;
    float*  part  = sm + SM_PART;
    float*  sc    = sm + SM_SC;
    float*  att   = sm + SM_ATT;

    const int cta = blockIdx.x;
    const int tid = threadIdx.x;
    const int w   = tid >> 5;
    const int lane = tid & 31;
    const int u0  = cta * UPC_;
    const int wn  = w & 1;            // n-tile (batch 16s)
    const int wkc = w >> 1;           // k-chunk (128s)
    const int ab  = cta & 31;         // attention batch
    const int aq  = cta >> 5;         // attention quarter (0..3)

    // -------- prologue: weights -> SMEM (pre-rounded to tf32) --------------
    for (int idx = tid; idx < 16 * 128; idx += 256) {
        int r = idx >> 7, kq = idx & 127;
        int row = ((r >> 2) * H_) + u0 + (r & 3);
        float4 v = *reinterpret_cast<const float4*>(Whh0 + (size_t)row * H_ + kq * 4);
        v.x = totf(v.x); v.y = totf(v.y); v.z = totf(v.z); v.w = totf(v.w);
        reinterpret_cast<float4*>(W0s + r * LDW0)[kq] = v;
    }
    for (int idx = tid; idx < 16 * 256; idx += 256) {
        int r = idx >> 8, kq = idx & 255;
        int row = ((r >> 2) * H_) + u0 + (r & 3);
        const float* src = (kq < 128)
            ? (Wih1 + (size_t)row * H_ + kq * 4)
            : (Whh1 + (size_t)row * H_ + (kq - 128) * 4);
        float4 v = *reinterpret_cast<const float4*>(src);
        v.x = totf(v.x); v.y = totf(v.y); v.z = totf(v.z); v.w = totf(v.w);
        reinterpret_cast<float4*>(W1s + r * LDW1)[kq] = v;
    }
    for (int idx = tid; idx < 4 * 256; idx += 256) {     // Wos fp32
        int r = idx >> 8, kq = idx & 255;
        reinterpret_cast<float4*>(Wos + r * 1024)[kq] =
            *reinterpret_cast<const float4*>(Wout + (size_t)(u0 + r) * (2 * H_) + kq * 4);
    }
    if (tid < 16) {
        int row = ((tid >> 2) * H_) + u0 + (tid & 3);
        bias1[tid] = bih[G4_ + row] + bhh[G4_ + row];
    }
    {   // cell state: cb[l*128 + ul*32 + b]
        int l = tid >> 7, ul = (tid >> 5) & 3, b = tid & 31;
        cb[tid] = c0in[(size_t)l * B_ * H_ + (size_t)b * H_ + u0 + ul];
    }
    if (tid < 32) {   // initial h -> slot 1 (read at tick 0 / tick 1)
        int b = tid;
#pragma unroll
        for (int ul = 0; ul < 4; ul++) {
            __stcg(&g_h0[1][b * H_ + u0 + ul], h0in[(size_t)b * H_ + u0 + ul]);
            __stcg(&g_h1[1][b * H_ + u0 + ul], h0in[(size_t)B_ * H_ + b * H_ + u0 + ul]);
        }
    }
    unsigned nbar = 0;
    gridbar(++nbar * CTAS_);

    // -------- pipelined main loop: tick tau computes
    //          L0(t=tau), L1(t=tau-1), attn(t=tau-2), attnout(t=tau-3) -------
    for (int tau = 0; tau < NT_; tau++) {
        const int sh0r = (tau + 1) & 1, sh0w = tau & 1;
        const int sh1r = tau & 1,       sh1w = (tau + 1) & 1;
        const int catw = tau & 1,       catr = (tau + 1) & 1;

        // (a) stage h0out_{tau-1} (shared B operand of L0 and L1-pass0)
        stage_rows(stg, reinterpret_cast<const float4*>(g_h0[sh0r]), tid);
        __syncthreads();

        // (b) L0 mma (acc0) + L1 pass0 mma (acc1) off the same stage
        wmma::fragment<wmma::accumulator, 16, 16, 8, float> acc0, acc1;
        wmma::fill_fragment(acc0, 0.f);
        wmma::fill_fragment(acc1, 0.f);
#pragma unroll
        for (int kk = 0; kk < 16; kk++) {
            int k = wkc * 128 + kk * 8;
            wmma::fragment<wmma::matrix_b, 16, 16, 8, wmma::precision::tf32, wmma::col_major> b;
            wmma::load_matrix_sync(b, stg + (wn * 16) * LDST + k, LDST);
            wmma::fragment<wmma::matrix_a, 16, 16, 8, wmma::precision::tf32, wmma::row_major> a0, a1;
            wmma::load_matrix_sync(a0, W0s + k, LDW0);
            wmma::load_matrix_sync(a1, W1s + k, LDW1);
            wmma::mma_sync(acc0, a0, b, acc0);
            wmma::mma_sync(acc1, a1, b, acc1);
        }
        __syncthreads();   // done reading stage

        // (c) restage with h1out_{tau-2} (L1 pass1 B operand + attn q rows)
        stage_rows(stg, reinterpret_cast<const float4*>(g_h1[sh1r]), tid);
        __syncthreads();

        // (d) L1 pass1 mma
#pragma unroll
        for (int kk = 0; kk < 16; kk++) {
            int k = wkc * 128 + kk * 8;
            wmma::fragment<wmma::matrix_b, 16, 16, 8, wmma::precision::tf32, wmma::col_major> b;
            wmma::load_matrix_sync(b, stg + (wn * 16) * LDST + k, LDST);
            wmma::fragment<wmma::matrix_a, 16, 16, 8, wmma::precision::tf32, wmma::row_major> a;
            wmma::load_matrix_sync(a, W1s + 512 + k, LDW1);
            wmma::mma_sync(acc1, a, b, acc1);
        }
        wmma::store_matrix_sync(pbuf0 + w * 256, acc0, 16, wmma::mem_row_major);
        wmma::store_matrix_sync(pbuf1 + w * 256, acc1, 16, wmma::mem_row_major);
        __syncthreads();

        // (e) k-chunk reductions
        if (tau <= 63)
            for (int o = tid; o < 512; o += 256) {
                int r = o >> 5, b = o & 31;
                float s = 0.f;
#pragma unroll
                for (int kc = 0; kc < 4; kc++)
                    s += pbuf0[((b >> 4) + 2 * kc) * 256 + r * 16 + (b & 15)];
                gbuf0[r * 32 + b] = s;
            }
        if (tau >= 1 && tau <= 64)
            for (int o = tid; o < 512; o += 256) {
                int r = o >> 5, b = o & 31;
                float s = 0.f;
#pragma unroll
                for (int kc = 0; kc < 4; kc++)
                    s += pbuf1[((b >> 4) + 2 * kc) * 256 + r * 16 + (b & 15)];
                gbuf1[r * 32 + b] = s;
            }
        __syncthreads();

        // (f) L0 epilogue on warps 0-3, L1 epilogue on warps 4-7 (parallel)
        if (tau <= 63 && tid < 128) {
            int t = tau;
            int ul = tid >> 5, b = tid & 31, u = u0 + ul;
            const float* pre = g_pre0 + (size_t)t * G4_ * B_;
            float gi = sigf(gbuf0[(0  + ul) * 32 + b] + __ldg(&pre[((size_t)0 * H_ + u) * B_ + b]));
            float gf = sigf(gbuf0[(4  + ul) * 32 + b] + __ldg(&pre[((size_t)1 * H_ + u) * B_ + b]));
            float gg = tanhf(gbuf0[(8  + ul) * 32 + b] + __ldg(&pre[((size_t)2 * H_ + u) * B_ + b]));
            float go = sigf(gbuf0[(12 + ul) * 32 + b] + __ldg(&pre[((size_t)3 * H_ + u) * B_ + b]));
            float c = gf * cb[ul * 32 + b] + gi * gg;
            cb[ul * 32 + b] = c;
            float h = go * tanhf(c);
            __stcg(&g_h0[sh0w][b * H_ + u], h);
            if (t == T_ - 1) {
                out[OFF_HT + (size_t)b * H_ + u] = h;
                out[OFF_CT + (size_t)b * H_ + u] = c;
            }
        }
        if (tau >= 1 && tau <= 64 && tid >= 128) {
            int t = tau - 1;
            int tt = tid - 128;
            int ul = tt >> 5, b = tt & 31, u = u0 + ul;
            float gi = sigf(gbuf1[(0  + ul) * 32 + b] + bias1[0  + ul]);
            float gf = sigf(gbuf1[(4  + ul) * 32 + b] + bias1[4  + ul]);
            float gg = tanhf(gbuf1[(8  + ul) * 32 + b] + bias1[8  + ul]);
            float go = sigf(gbuf1[(12 + ul) * 32 + b] + bias1[12 + ul]);
            float c = gf * cb[128 + ul * 32 + b] + gi * gg;
            cb[128 + ul * 32 + b] = c;
            float h = go * tanhf(c);
            __stcg(&g_h1[sh1w][b * H_ + u], h);
            if (t == T_ - 1) {
                out[OFF_HT + (size_t)B_ * H_ + (size_t)b * H_ + u] = h;
                out[OFF_CT + (size_t)B_ * H_ + (size_t)b * H_ + u] = c;
            }
        }

        // (g) attention for t = tau-2 (stg still holds h1out_{tau-2})
        if (tau >= 2 && tau <= 65) {
            const float4* qs4 = reinterpret_cast<const float4*>(stg + ab * LDST);
#pragma unroll
            for (int si = 0; si < 8; si++) {
                int s = w * 8 + si;
                const float4* c2r = reinterpret_cast<const float4*>(
                    g_c2 + (size_t)(ab * S_ + s) * H_);
                float a = 0.f;
#pragma unroll
                for (int kq = lane; kq < 128; kq += 32) {
                    float4 cv = __ldg(&c2r[kq]);
                    float4 qv = qs4[kq];
                    a += cv.x * qv.x + cv.y * qv.y + cv.z * qv.z + cv.w * qv.w;
                }
#pragma unroll
                for (int off = 16; off; off >>= 1) a += __shfl_xor_sync(0xffffffffu, a, off);
                if (lane == 0) sc[s] = a;
            }
            __syncthreads();
            if (tid < 32) {
                float v0 = sc[tid], v1 = sc[tid + 32];
                float m = fmaxf(v0, v1);
#pragma unroll
                for (int off = 16; off; off >>= 1) m = fmaxf(m, __shfl_xor_sync(0xffffffffu, m, off));
                float e0 = __expf(v0 - m), e1 = __expf(v1 - m);
                float s2 = e0 + e1;
#pragma unroll
                for (int off = 16; off; off >>= 1) s2 += __shfl_xor_sync(0xffffffffu, s2, off);
                float inv = 1.f / s2;
                att[tid] = e0 * inv; att[tid + 32] = e1 * inv;
                if (aq == 0 && tau == 65) {
                    out[OFF_ATTN + ab * S_ + tid]      = e0 * inv;
                    out[OFF_ATTN + ab * S_ + tid + 32] = e1 * inv;
                }
            }
            __syncthreads();
            {   // ctx: quarter handles h in [aq*128, aq*128+128); 2 threads per h
                int h = aq * 128 + (tid >> 1);
                int s0 = (tid & 1) * 32;
                const float* cx = context + (size_t)ab * S_ * H_ + h;
                float a = 0.f;
#pragma unroll 8
                for (int s = s0; s < s0 + 32; s++) a += att[s] * cx[(size_t)s * H_];
                a += __shfl_xor_sync(0xffffffffu, a, 1);
                if ((tid & 1) == 0) {
                    float* catp = reinterpret_cast<float*>(g_cat4[catw]);
                    __stcg(&catp[((h >> 2) * 32 + ab) * 4 + (h & 3)], a);
                    int h2 = H_ + h;
                    float hv = __ldcg(&g_h1[sh1r][ab * H_ + h]);
                    __stcg(&catp[((h2 >> 2) * 32 + ab) * 4 + (h2 & 3)], hv);
                }
            }
        }

        // (h) attention-out for t = tau-3: warp w owns k-quads [w*16, w*16+16)
        //     per half; computes partials for ALL 4 output rows (no dup L2 reads)
        if (tau >= 3) {
            const int tO = tau - 3;
            float racc[4] = {0.f, 0.f, 0.f, 0.f};
            const int i0 = w * 16;
#pragma unroll
            for (int half = 0; half < 2; half++) {
                const float4* catp = g_cat4[catr] + half * 4096;
                const float4* wr = reinterpret_cast<const float4*>(Wos + half * H_);
#pragma unroll 4
                for (int i = 0; i < 16; i++) {
                    float4 h = __ldcg(&catp[(i0 + i) * 32 + lane]);
#pragma unroll
                    for (int row = 0; row < 4; row++) {
                        float4 x = wr[row * 256 + i0 + i];   // Wos row stride 1024 f = 256 f4
                        racc[row] += x.x * h.x + x.y * h.y + x.z * h.z + x.w * h.w;
                    }
                }
            }
#pragma unroll
            for (int row = 0; row < 4; row++)
                part[row * 256 + w * 32 + lane] = racc[row];
            __syncthreads();
            if (tid < 128) {
                int r = tid >> 5, b = tid & 31;
                float v = 0.f;
#pragma unroll
                for (int ww = 0; ww < 8; ww++) v += part[r * 256 + ww * 32 + b];
                v = tanhf(v);
                g_outs_bf[((size_t)tO * B_ + b) * H_ + u0 + r] = __float2bfloat16(v);
            }
        }

        if (tau != NT_ - 1) gridbar(++nbar * CTAS_);
    }
}

// ---------------- vocab GEMM: logits = outs_bf @ wlin_bf^T ------------------
__global__ void __launch_bounds__(256)
k_wmma(float* __restrict__ C) {
    __shared__ __align__(16) __nv_bfloat16 As[2][128 * 40];
    __shared__ __align__(16) __nv_bfloat16 Bs[2][128 * 40];
    const int m0 = blockIdx.y * 128, n0 = blockIdx.x * 128;
    const int tid = threadIdx.x;
    const int wid = tid >> 5;
    const int wm = (wid >> 2) * 64, wn = (wid & 3) * 32;
    wmma::fragment<wmma::accumulator, 16, 16, 16, float> acc[4][2];
#pragma unroll
    for (int i = 0; i < 4; i++)
#pragma unroll
        for (int j = 0; j < 2; j++) wmma::fill_fragment(acc[i][j], 0.f);
    const int r = tid >> 1;
    const int c = (tid & 1) * 16;

#pragma unroll
    for (int q = 0; q < 2; q++) {
        *reinterpret_cast<uint4*>(&As[0][r * 40 + c + q * 8]) =
            *reinterpret_cast<const uint4*>(&g_outs_bf[(size_t)(m0 + r) * D_ + c + q * 8]);
        *reinterpret_cast<uint4*>(&Bs[0][r * 40 + c + q * 8]) =
            *reinterpret_cast<const uint4*>(&g_wlin_bf[(size_t)(n0 + r) * D_ + c + q * 8]);
    }
    __syncthreads();

    int buf = 0;
    for (int k0 = 0; k0 < D_; k0 += 32) {
        uint4 ra[2], rb[2];
        const bool has_next = (k0 + 32 < D_);
        if (has_next) {
#pragma unroll
            for (int q = 0; q < 2; q++) {
                ra[q] = *reinterpret_cast<const uint4*>(
                    &g_outs_bf[(size_t)(m0 + r) * D_ + k0 + 32 + c + q * 8]);
                rb[q] = *reinterpret_cast<const uint4*>(
                    &g_wlin_bf[(size_t)(n0 + r) * D_ + k0 + 32 + c + q * 8]);
            }
        }
#pragma unroll
        for (int sub = 0; sub < 2; sub++) {
            wmma::fragment<wmma::matrix_b, 16, 16, 16, __nv_bfloat16, wmma::col_major> bf[2];
#pragma unroll
            for (int j = 0; j < 2; j++)
                wmma::load_matrix_sync(bf[j], &Bs[buf][(wn + j * 16) * 40 + sub * 16], 40);
#pragma unroll
            for (int i = 0; i < 4; i++) {
                wmma::fragment<wmma::matrix_a, 16, 16, 16, __nv_bfloat16, wmma::row_major> af;
                wmma::load_matrix_sync(af, &As[buf][(wm + i * 16) * 40 + sub * 16], 40);
#pragma unroll
                for (int j = 0; j < 2; j++) wmma::mma_sync(acc[i][j], af, bf[j], acc[i][j]);
            }
        }
        if (has_next) {
#pragma unroll
            for (int q = 0; q < 2; q++) {
                *reinterpret_cast<uint4*>(&As[buf ^ 1][r * 40 + c + q * 8]) = ra[q];
                *reinterpret_cast<uint4*>(&Bs[buf ^ 1][r * 40 + c + q * 8]) = rb[q];
            }
        }
        __syncthreads();
        buf ^= 1;
    }
#pragma unroll
    for (int i = 0; i < 4; i++)
#pragma unroll
        for (int j = 0; j < 2; j++)
            wmma::store_matrix_sync(C + (size_t)(m0 + wm + i * 16) * V_ + n0 + wn + j * 16,
                                    acc[i][j], V_, wmma::mem_row_major);
}

// ---------------- log_softmax (adds b_lin, in-place, float4 vectorized) -----
__global__ void k_logsoftmax(float* __restrict__ logits, const float* __restrict__ b_lin) {
    const int row = blockIdx.x;
    float* p = logits + (size_t)row * V_;
    float4* p4 = reinterpret_cast<float4*>(p);
    const float4* b4 = reinterpret_cast<const float4*>(b_lin);
    const int tid = threadIdx.x;
    float m = -1e30f, s = 0.f;
    for (int v = tid; v < V_ / 4; v += 256) {
        float4 x = p4[v], bb = b4[v];
        float e[4] = {x.x + bb.x, x.y + bb.y, x.z + bb.z, x.w + bb.w};
#pragma unroll
        for (int q = 0; q < 4; q++) {
            if (e[q] > m) { s = s * __expf(m - e[q]) + 1.f; m = e[q]; }
            else          { s += __expf(e[q] - m); }
        }
    }
    __shared__ float sm[256], ss[256];
    sm[tid] = m; ss[tid] = s;
    __syncthreads();
    for (int off = 128; off; off >>= 1) {
        if (tid < off) {
            float m2 = sm[tid + off], s2 = ss[tid + off];
            float M = fmaxf(sm[tid], m2);
            ss[tid] = ss[tid] * __expf(sm[tid] - M) + s2 * __expf(m2 - M);
            sm[tid] = M;
        }
        __syncthreads();
    }
    float lse = sm[0] + logf(ss[0]);
    for (int v = tid; v < V_ / 4; v += 256) {
        float4 x = p4[v], bb = b4[v];
        x.x = x.x + bb.x - lse; x.y = x.y + bb.y - lse;
        x.z = x.z + bb.z - lse; x.w = x.w + bb.w - lse;
        p4[v] = x;
    }
}

// ---------------- host driver ----------------------------------------------
extern "C" void kernel_launch(void* const* d_in, const int* in_sizes, int n_in,
                              void* d_out, int out_size) {
    const int*   tokens     = (const int*)d_in[0];
    const float* h0         = (const float*)d_in[1];
    const float* c0         = (const float*)d_in[2];
    const float* context    = (const float*)d_in[3];
    const float* embedding  = (const float*)d_in[4];
    const float* Wih        = (const float*)d_in[5];
    const float* Whh        = (const float*)d_in[6];
    const float* bih        = (const float*)d_in[7];
    const float* bhh        = (const float*)d_in[8];
    const float* W_attn_in  = (const float*)d_in[9];
    const float* W_attn_out = (const float*)d_in[10];
    const float* W_lin      = (const float*)d_in[11];
    const float* b_lin      = (const float*)d_in[12];
    float* out = (float*)d_out;

    cudaFuncSetAttribute(k_scan, cudaFuncAttributeMaxDynamicSharedMemorySize, SMEM_BYTES);

    const float* Wih1 = Wih + (size_t)G4_ * D_;
    const float* Whh1 = Whh + (size_t)G4_ * H_;

    k_reset<<<1, 1>>>();
    k_convert_wlin<<<(V_ * D_ / 4 + 255) / 256, 256>>>(W_lin);
    k_gemm_pre<<<dim3(G4_ / 128, MR_ / 128), 256>>>(tokens, embedding, Wih, bih, bhh);
    k_c2<<<dim3(H_ / 128, (B_ * S_) / 128), 256>>>(context, W_attn_in);
    k_scan<<<CTAS_, 256, SMEM_BYTES>>>(Whh, Wih1, Whh1, bih, bhh, context,
                                       W_attn_out, h0, c0, out);
    k_wmma<<<dim3(V_ / 128, MR_ / 128), 256>>>(out);
    k_logsoftmax<<<MR_, 256>>>(out, b_lin);
}

// round 13
// speedup vs baseline: 1.5035x; 1.1476x over previous
#include <cuda_runtime.h>
#include <cuda_bf16.h>
#include <mma.h>
using namespace nvcuda;

#define B_  32
#define T_  64
#define S_  64
#define H_  512
#define D_  512
#define V_  32000
#define G4_ 2048            // 4*H
#define MR_ 2048            // T*B rows

#define CTAS_ 128
#define UPC_  4             // units per CTA (both layers)
#define NT_   67            // pipelined ticks = T + 3

// d_out layout (f32): log_probs [T,B,V], hT [2,B,H], cT [2,B,H], attn [B,S]
#define OFF_HT   ((size_t)T_ * B_ * V_)
#define OFF_CT   (OFF_HT + (size_t)2 * B_ * H_)
#define OFF_ATTN (OFF_CT + (size_t)2 * B_ * H_)

// ---------------- device scratch -------------------------------------------
__device__ float g_pre0[(size_t)T_ * G4_ * B_];       // [t][gate_row][b]  16MB
__device__ float g_c2[(size_t)B_ * S_ * H_];          // context @ W_attn_in 4MB
__device__ float g_h0[2][B_ * H_];                    // h layer0, [b][k] row-major
__device__ float g_h1[2][B_ * H_];                    // h layer1, [b][k] row-major
__device__ float4 g_cat4[2][(2 * H_ / 4) * B_];       // [slot][h-quad][b] k4 layout
__device__ __nv_bfloat16 g_outs_bf[(size_t)MR_ * H_];
__device__ __nv_bfloat16 g_wlin_bf[(size_t)V_ * D_];
__device__ unsigned g_bar;

__device__ __forceinline__ float sigf(float x) { return 1.f / (1.f + __expf(-x)); }
__device__ __forceinline__ float totf(float x) { return wmma::__float_to_tf32(x); }

__global__ void k_reset() { g_bar = 0u; }

// ---------------- W_lin fp32 -> bf16 ---------------------------------------
__global__ void k_convert_wlin(const float* __restrict__ w) {
    int i = blockIdx.x * blockDim.x + threadIdx.x;
    if (i < (V_ * D_) / 4) {
        float4 v = reinterpret_cast<const float4*>(w)[i];
        __nv_bfloat162* o = reinterpret_cast<__nv_bfloat162*>(g_wlin_bf);
        o[i * 2]     = __floats2bfloat162_rn(v.x, v.y);
        o[i * 2 + 1] = __floats2bfloat162_rn(v.z, v.w);
    }
}

// ---------------- embed + input projection (tf32 WMMA) ----------------------
__global__ void __launch_bounds__(256)
k_gemm_pre(const int* __restrict__ tokens,
           const float* __restrict__ embedding,
           const float* __restrict__ Wih0,
           const float* __restrict__ bih0,
           const float* __restrict__ bhh0) {
    __shared__ float As[128 * 36];
    __shared__ float Bs[128 * 36];
    __shared__ float scr[8 * 320];
    __shared__ float bsh[128];
    __shared__ int   toks[128];
    const int tid = threadIdx.x;
    const int w   = tid >> 5;
    const int lane = tid & 31;
    const int m0 = blockIdx.y * 128, n0 = blockIdx.x * 128;
    const int wm = (w >> 2) * 64, wn = (w & 3) * 32;

    if (tid < 128) {
        int m = m0 + tid;
        toks[tid] = tokens[(m & 31) * T_ + (m >> 5)];
        bsh[tid] = bih0[n0 + tid] + bhh0[n0 + tid];
    }
    __syncthreads();

    wmma::fragment<wmma::accumulator, 16, 16, 8, float> acc[4][2];
#pragma unroll
    for (int i = 0; i < 4; i++)
#pragma unroll
        for (int j = 0; j < 2; j++) wmma::fill_fragment(acc[i][j], 0.f);

    for (int k0 = 0; k0 < D_; k0 += 32) {
#pragma unroll
        for (int it = 0; it < 4; it++) {
            int idx = tid + it * 256;
            int r = idx >> 3, c = (idx & 7) * 4;
            float4 va = *reinterpret_cast<const float4*>(
                embedding + (size_t)toks[r] * D_ + k0 + c);
            As[r * 36 + c] = totf(va.x); As[r * 36 + c + 1] = totf(va.y);
            As[r * 36 + c + 2] = totf(va.z); As[r * 36 + c + 3] = totf(va.w);
            float4 vb = *reinterpret_cast<const float4*>(
                Wih0 + (size_t)(n0 + r) * D_ + k0 + c);
            Bs[r * 36 + c] = totf(vb.x); Bs[r * 36 + c + 1] = totf(vb.y);
            Bs[r * 36 + c + 2] = totf(vb.z); Bs[r * 36 + c + 3] = totf(vb.w);
        }
        __syncthreads();
#pragma unroll
        for (int kk = 0; kk < 4; kk++) {
            wmma::fragment<wmma::matrix_b, 16, 16, 8, wmma::precision::tf32, wmma::col_major> b[2];
#pragma unroll
            for (int j = 0; j < 2; j++)
                wmma::load_matrix_sync(b[j], Bs + (wn + j * 16) * 36 + kk * 8, 36);
#pragma unroll
            for (int i = 0; i < 4; i++) {
                wmma::fragment<wmma::matrix_a, 16, 16, 8, wmma::precision::tf32, wmma::row_major> a;
                wmma::load_matrix_sync(a, As + (wm + i * 16) * 36 + kk * 8, 36);
#pragma unroll
                for (int j = 0; j < 2; j++) wmma::mma_sync(acc[i][j], a, b[j], acc[i][j]);
            }
        }
        __syncthreads();
    }
#pragma unroll
    for (int i = 0; i < 4; i++)
#pragma unroll
        for (int j = 0; j < 2; j++) {
            wmma::store_matrix_sync(scr + w * 320, acc[i][j], 20, wmma::mem_row_major);
            __syncwarp();
            int c = lane >> 1;
            int r0 = (lane & 1) * 8;
            int n = n0 + wn + j * 16 + c;
            int mbase = m0 + wm + i * 16 + r0;
            int t = mbase >> 5, b0 = mbase & 31;
            float bias = bsh[wn + j * 16 + c];
            float* dst = g_pre0 + ((size_t)t * G4_ + n) * B_ + b0;
#pragma unroll
            for (int rr = 0; rr < 8; rr++)
                dst[rr] = scr[w * 320 + (r0 + rr) * 20 + c] + bias;
            __syncwarp();
        }
}

// ---------------- C2 = context @ W_attn_in (tf32 WMMA) ----------------------
__global__ void __launch_bounds__(256)
k_c2(const float* __restrict__ A, const float* __restrict__ Wq) {
    __shared__ float As[128 * 36];
    __shared__ float Bs[32 * 132];
    const int tid = threadIdx.x;
    const int w   = tid >> 5;
    const int m0 = blockIdx.y * 128, n0 = blockIdx.x * 128;
    const int wm = (w >> 2) * 64, wn = (w & 3) * 32;

    wmma::fragment<wmma::accumulator, 16, 16, 8, float> acc[4][2];
#pragma unroll
    for (int i = 0; i < 4; i++)
#pragma unroll
        for (int j = 0; j < 2; j++) wmma::fill_fragment(acc[i][j], 0.f);

    for (int k0 = 0; k0 < H_; k0 += 32) {
#pragma unroll
        for (int it = 0; it < 4; it++) {
            int idx = tid + it * 256;
            int r = idx >> 3, c = (idx & 7) * 4;
            float4 va = *reinterpret_cast<const float4*>(
                A + (size_t)(m0 + r) * H_ + k0 + c);
            As[r * 36 + c] = totf(va.x); As[r * 36 + c + 1] = totf(va.y);
            As[r * 36 + c + 2] = totf(va.z); As[r * 36 + c + 3] = totf(va.w);
        }
#pragma unroll
        for (int it = 0; it < 4; it++) {
            int idx = tid + it * 256;
            int r = idx >> 5, c = (idx & 31) * 4;
            float4 vb = *reinterpret_cast<const float4*>(
                Wq + (size_t)(k0 + r) * H_ + n0 + c);
            Bs[r * 132 + c] = totf(vb.x); Bs[r * 132 + c + 1] = totf(vb.y);
            Bs[r * 132 + c + 2] = totf(vb.z); Bs[r * 132 + c + 3] = totf(vb.w);
        }
        __syncthreads();
#pragma unroll
        for (int kk = 0; kk < 4; kk++) {
            wmma::fragment<wmma::matrix_b, 16, 16, 8, wmma::precision::tf32, wmma::row_major> b[2];
#pragma unroll
            for (int j = 0; j < 2; j++)
                wmma::load_matrix_sync(b[j], Bs + kk * 8 * 132 + wn + j * 16, 132);
#pragma unroll
            for (int i = 0; i < 4; i++) {
                wmma::fragment<wmma::matrix_a, 16, 16, 8, wmma::precision::tf32, wmma::row_major> a;
                wmma::load_matrix_sync(a, As + (wm + i * 16) * 36 + kk * 8, 36);
#pragma unroll
                for (int j = 0; j < 2; j++) wmma::mma_sync(acc[i][j], a, b[j], acc[i][j]);
            }
        }
        __syncthreads();
    }
#pragma unroll
    for (int i = 0; i < 4; i++)
#pragma unroll
        for (int j = 0; j < 2; j++)
            wmma::store_matrix_sync(g_c2 + (size_t)(m0 + wm + i * 16) * H_ + n0 + wn + j * 16,
                                    acc[i][j], H_, wmma::mem_row_major);
}

// ---------------- pipelined persistent scan kernel ---------------------------
// SMEM float offsets
#define SM_W0    0                          // 16 x 520
#define SM_W1    8320                       // 16 x 1040
#define SM_WOS   24960                      // 4 x 1024
#define SM_STAGE 29056                      // 32 x 520
#define SM_PBUF0 45696                      // 8 x 256
#define SM_PBUF1 47744                      // 8 x 256
#define SM_GBUF0 49792                      // 16 x 32
#define SM_GBUF1 50304                      // 16 x 32
#define SM_CB    50816                      // 2 x 4 x 32
#define SM_B1    51072                      // 16
#define SM_PART  51088                      // 4 x 8 x 32 = 1024
#define SM_SC    52112                      // 64
#define SM_ATT   52176                      // 64
#define SMEM_FLOATS 52240
#define SMEM_BYTES  (SMEM_FLOATS * 4)

#define LDW0  520
#define LDW1  1040
#define LDST  520

__device__ __forceinline__ void gridbar(unsigned target) {
    __threadfence();
    __syncthreads();
    if (threadIdx.x == 0) {
        atomicAdd(&g_bar, 1u);
        volatile unsigned* vb = &g_bar;
        while (*vb < target) __nanosleep(32);
    }
    __syncthreads();
}

// copy 32x512 row-major h into padded stage [b][520], rounding to tf32
__device__ __forceinline__ void stage_rows(float* stg, const float4* src, int tid) {
    for (int idx = tid; idx < 4096; idx += 256) {
        int b = idx >> 7, j = idx & 127;
        float4 v = __ldcg(&src[idx]);
        v.x = totf(v.x); v.y = totf(v.y); v.z = totf(v.z); v.w = totf(v.w);
        reinterpret_cast<float4*>(stg + b * LDST)[j] = v;
    }
}

__global__ void __launch_bounds__(256, 1)
k_scan(const float* __restrict__ Whh0, const float* __restrict__ Wih1,
       const float* __restrict__ Whh1, const float* __restrict__ bih,
       const float* __restrict__ bhh, const float* __restrict__ context,
       const float* __restrict__ Wout, const float* __restrict__ h0in,
       const float* __restrict__ c0in, float* __restrict__ out) {
    extern __shared__ float sm[];
    float*  W0s   = sm + SM_W0;
    float*  W1s   = sm + SM_W1;
    float*  Wos   = sm + SM_WOS;
    float*  stg   = sm + SM_STAGE;
    float*  pbuf0 = sm + SM_PBUF0;
    float*  pbuf1 = sm + SM_PBUF1;
    float*  gbuf0 = sm + SM_GBUF0;
    float*  gbuf1 = sm + SM_GBUF1;
    float*  cb    = sm + SM_CB;
    float*  bias1 = sm + SM_B1;
    float*  part  = sm + SM_PART;
    float*  sc    = sm + SM_SC;
    float*  att   = sm + SM_ATT;

    const int cta = blockIdx.x;
    const int tid = threadIdx.x;
    const int w   = tid >> 5;
    const int lane = tid & 31;
    const int u0  = cta * UPC_;
    const int wn  = w & 1;            // n-tile (batch 16s)
    const int wkc = w >> 1;           // k-chunk (128s)
    const int ab  = cta & 31;         // attention batch
    const int aq  = cta >> 5;         // attention quarter (0..3)

    // -------- prologue: weights -> SMEM (pre-rounded to tf32) --------------
    for (int idx = tid; idx < 16 * 128; idx += 256) {
        int r = idx >> 7, kq = idx & 127;
        int row = ((r >> 2) * H_) + u0 + (r & 3);
        float4 v = *reinterpret_cast<const float4*>(Whh0 + (size_t)row * H_ + kq * 4);
        v.x = totf(v.x); v.y = totf(v.y); v.z = totf(v.z); v.w = totf(v.w);
        reinterpret_cast<float4*>(W0s + r * LDW0)[kq] = v;
    }
    for (int idx = tid; idx < 16 * 256; idx += 256) {
        int r = idx >> 8, kq = idx & 255;
        int row = ((r >> 2) * H_) + u0 + (r & 3);
        const float* src = (kq < 128)
            ? (Wih1 + (size_t)row * H_ + kq * 4)
            : (Whh1 + (size_t)row * H_ + (kq - 128) * 4);
        float4 v = *reinterpret_cast<const float4*>(src);
        v.x = totf(v.x); v.y = totf(v.y); v.z = totf(v.z); v.w = totf(v.w);
        reinterpret_cast<float4*>(W1s + r * LDW1)[kq] = v;
    }
    for (int idx = tid; idx < 4 * 256; idx += 256) {     // Wos fp32
        int r = idx >> 8, kq = idx & 255;
        reinterpret_cast<float4*>(Wos + r * 1024)[kq] =
            *reinterpret_cast<const float4*>(Wout + (size_t)(u0 + r) * (2 * H_) + kq * 4);
    }
    if (tid < 16) {
        int row = ((tid >> 2) * H_) + u0 + (tid & 3);
        bias1[tid] = bih[G4_ + row] + bhh[G4_ + row];
    }
    {   // cell state: cb[l*128 + ul*32 + b]
        int l = tid >> 7, ul = (tid >> 5) & 3, b = tid & 31;
        cb[tid] = c0in[(size_t)l * B_ * H_ + (size_t)b * H_ + u0 + ul];
    }
    if (tid < 32) {   // initial h -> slot 1 (read at tick 0 / tick 1)
        int b = tid;
#pragma unroll
        for (int ul = 0; ul < 4; ul++) {
            __stcg(&g_h0[1][b * H_ + u0 + ul], h0in[(size_t)b * H_ + u0 + ul]);
            __stcg(&g_h1[1][b * H_ + u0 + ul], h0in[(size_t)B_ * H_ + b * H_ + u0 + ul]);
        }
    }
    unsigned nbar = 0;
    gridbar(++nbar * CTAS_);

    // -------- pipelined main loop: tick tau computes
    //          L0(t=tau), L1(t=tau-1), attn(t=tau-2), attnout(t=tau-3) -------
    for (int tau = 0; tau < NT_; tau++) {
        const int sh0r = (tau + 1) & 1, sh0w = tau & 1;
        const int sh1r = tau & 1,       sh1w = (tau + 1) & 1;
        const int catw = tau & 1,       catr = (tau + 1) & 1;

        // (a) stage h0out_{tau-1}; ALSO prefetch h1out_{tau-2} into registers
        //     (both published before this tick's opening barrier)
        stage_rows(stg, reinterpret_cast<const float4*>(g_h0[sh0r]), tid);
        float4 pf[16];
        {
            const float4* h1src = reinterpret_cast<const float4*>(g_h1[sh1r]);
#pragma unroll
            for (int q = 0; q < 16; q++) pf[q] = __ldcg(&h1src[tid + q * 256]);
        }
        __syncthreads();

        // (b) L0 mma (acc0) + L1 pass0 mma (acc1) off the same stage
        wmma::fragment<wmma::accumulator, 16, 16, 8, float> acc0, acc1;
        wmma::fill_fragment(acc0, 0.f);
        wmma::fill_fragment(acc1, 0.f);
#pragma unroll
        for (int kk = 0; kk < 16; kk++) {
            int k = wkc * 128 + kk * 8;
            wmma::fragment<wmma::matrix_b, 16, 16, 8, wmma::precision::tf32, wmma::col_major> b;
            wmma::load_matrix_sync(b, stg + (wn * 16) * LDST + k, LDST);
            wmma::fragment<wmma::matrix_a, 16, 16, 8, wmma::precision::tf32, wmma::row_major> a0, a1;
            wmma::load_matrix_sync(a0, W0s + k, LDW0);
            wmma::load_matrix_sync(a1, W1s + k, LDW1);
            wmma::mma_sync(acc0, a0, b, acc0);
            wmma::mma_sync(acc1, a1, b, acc1);
        }
        __syncthreads();   // done reading stage

        // (c) write prefetched h1 into stage (pure STS, no L2 on critical path)
#pragma unroll
        for (int q = 0; q < 16; q++) {
            int idx = tid + q * 256;
            float4 v = pf[q];
            v.x = totf(v.x); v.y = totf(v.y); v.z = totf(v.z); v.w = totf(v.w);
            reinterpret_cast<float4*>(stg + (idx >> 7) * LDST)[idx & 127] = v;
        }
        __syncthreads();

        // (d) L1 pass1 mma
#pragma unroll
        for (int kk = 0; kk < 16; kk++) {
            int k = wkc * 128 + kk * 8;
            wmma::fragment<wmma::matrix_b, 16, 16, 8, wmma::precision::tf32, wmma::col_major> b;
            wmma::load_matrix_sync(b, stg + (wn * 16) * LDST + k, LDST);
            wmma::fragment<wmma::matrix_a, 16, 16, 8, wmma::precision::tf32, wmma::row_major> a;
            wmma::load_matrix_sync(a, W1s + 512 + k, LDW1);
            wmma::mma_sync(acc1, a, b, acc1);
        }
        wmma::store_matrix_sync(pbuf0 + w * 256, acc0, 16, wmma::mem_row_major);
        wmma::store_matrix_sync(pbuf1 + w * 256, acc1, 16, wmma::mem_row_major);
        __syncthreads();

        // (e) k-chunk reductions
        if (tau <= 63)
            for (int o = tid; o < 512; o += 256) {
                int r = o >> 5, b = o & 31;
                float s = 0.f;
#pragma unroll
                for (int kc = 0; kc < 4; kc++)
                    s += pbuf0[((b >> 4) + 2 * kc) * 256 + r * 16 + (b & 15)];
                gbuf0[r * 32 + b] = s;
            }
        if (tau >= 1 && tau <= 64)
            for (int o = tid; o < 512; o += 256) {
                int r = o >> 5, b = o & 31;
                float s = 0.f;
#pragma unroll
                for (int kc = 0; kc < 4; kc++)
                    s += pbuf1[((b >> 4) + 2 * kc) * 256 + r * 16 + (b & 15)];
                gbuf1[r * 32 + b] = s;
            }
        __syncthreads();

        // (f) L0 epilogue on warps 0-3, L1 epilogue on warps 4-7 (parallel)
        if (tau <= 63 && tid < 128) {
            int t = tau;
            int ul = tid >> 5, b = tid & 31, u = u0 + ul;
            const float* pre = g_pre0 + (size_t)t * G4_ * B_;
            float gi = sigf(gbuf0[(0  + ul) * 32 + b] + __ldg(&pre[((size_t)0 * H_ + u) * B_ + b]));
            float gf = sigf(gbuf0[(4  + ul) * 32 + b] + __ldg(&pre[((size_t)1 * H_ + u) * B_ + b]));
            float gg = tanhf(gbuf0[(8  + ul) * 32 + b] + __ldg(&pre[((size_t)2 * H_ + u) * B_ + b]));
            float go = sigf(gbuf0[(12 + ul) * 32 + b] + __ldg(&pre[((size_t)3 * H_ + u) * B_ + b]));
            float c = gf * cb[ul * 32 + b] + gi * gg;
            cb[ul * 32 + b] = c;
            float h = go * tanhf(c);
            __stcg(&g_h0[sh0w][b * H_ + u], h);
            if (t == T_ - 1) {
                out[OFF_HT + (size_t)b * H_ + u] = h;
                out[OFF_CT + (size_t)b * H_ + u] = c;
            }
        }
        if (tau >= 1 && tau <= 64 && tid >= 128) {
            int t = tau - 1;
            int tt = tid - 128;
            int ul = tt >> 5, b = tt & 31, u = u0 + ul;
            float gi = sigf(gbuf1[(0  + ul) * 32 + b] + bias1[0  + ul]);
            float gf = sigf(gbuf1[(4  + ul) * 32 + b] + bias1[4  + ul]);
            float gg = tanhf(gbuf1[(8  + ul) * 32 + b] + bias1[8  + ul]);
            float go = sigf(gbuf1[(12 + ul) * 32 + b] + bias1[12 + ul]);
            float c = gf * cb[128 + ul * 32 + b] + gi * gg;
            cb[128 + ul * 32 + b] = c;
            float h = go * tanhf(c);
            __stcg(&g_h1[sh1w][b * H_ + u], h);
            if (t == T_ - 1) {
                out[OFF_HT + (size_t)B_ * H_ + (size_t)b * H_ + u] = h;
                out[OFF_CT + (size_t)B_ * H_ + (size_t)b * H_ + u] = c;
            }
        }

        // (g) attention for t = tau-2 (stg holds h1out_{tau-2})
        if (tau >= 2 && tau <= 65) {
            const float4* qs4 = reinterpret_cast<const float4*>(stg + ab * LDST);
#pragma unroll
            for (int si = 0; si < 8; si++) {
                int s = w * 8 + si;
                const float4* c2r = reinterpret_cast<const float4*>(
                    g_c2 + (size_t)(ab * S_ + s) * H_);
                float a = 0.f;
#pragma unroll
                for (int kq = lane; kq < 128; kq += 32) {
                    float4 cv = __ldg(&c2r[kq]);
                    float4 qv = qs4[kq];
                    a += cv.x * qv.x + cv.y * qv.y + cv.z * qv.z + cv.w * qv.w;
                }
#pragma unroll
                for (int off = 16; off; off >>= 1) a += __shfl_xor_sync(0xffffffffu, a, off);
                if (lane == 0) sc[s] = a;
            }
            __syncthreads();
            if (tid < 32) {
                float v0 = sc[tid], v1 = sc[tid + 32];
                float m = fmaxf(v0, v1);
#pragma unroll
                for (int off = 16; off; off >>= 1) m = fmaxf(m, __shfl_xor_sync(0xffffffffu, m, off));
                float e0 = __expf(v0 - m), e1 = __expf(v1 - m);
                float s2 = e0 + e1;
#pragma unroll
                for (int off = 16; off; off >>= 1) s2 += __shfl_xor_sync(0xffffffffu, s2, off);
                float inv = 1.f / s2;
                att[tid] = e0 * inv; att[tid + 32] = e1 * inv;
                if (aq == 0 && tau == 65) {
                    out[OFF_ATTN + ab * S_ + tid]      = e0 * inv;
                    out[OFF_ATTN + ab * S_ + tid + 32] = e1 * inv;
                }
            }
            __syncthreads();
            {   // ctx: quarter handles h in [aq*128, aq*128+128); 2 threads per h
                int h = aq * 128 + (tid >> 1);
                int s0 = (tid & 1) * 32;
                const float* cx = context + (size_t)ab * S_ * H_ + h;
                float a = 0.f;
#pragma unroll 8
                for (int s = s0; s < s0 + 32; s++) a += att[s] * cx[(size_t)s * H_];
                a += __shfl_xor_sync(0xffffffffu, a, 1);
                if ((tid & 1) == 0) {
                    float* catp = reinterpret_cast<float*>(g_cat4[catw]);
                    __stcg(&catp[((h >> 2) * 32 + ab) * 4 + (h & 3)], a);
                    int h2 = H_ + h;
                    float hv = __ldcg(&g_h1[sh1r][ab * H_ + h]);
                    __stcg(&catp[((h2 >> 2) * 32 + ab) * 4 + (h2 & 3)], hv);
                }
            }
        }

        // (h) attention-out for t = tau-3: warp w owns k-quads [w*16, w*16+16)
        if (tau >= 3) {
            const int tO = tau - 3;
            float racc[4] = {0.f, 0.f, 0.f, 0.f};
            const int i0 = w * 16;
#pragma unroll
            for (int half = 0; half < 2; half++) {
                const float4* catp = g_cat4[catr] + half * 4096;
                const float4* wr = reinterpret_cast<const float4*>(Wos + half * H_);
#pragma unroll 4
                for (int i = 0; i < 16; i++) {
                    float4 h = __ldcg(&catp[(i0 + i) * 32 + lane]);
#pragma unroll
                    for (int row = 0; row < 4; row++) {
                        float4 x = wr[row * 256 + i0 + i];
                        racc[row] += x.x * h.x + x.y * h.y + x.z * h.z + x.w * h.w;
                    }
                }
            }
#pragma unroll
            for (int row = 0; row < 4; row++)
                part[row * 256 + w * 32 + lane] = racc[row];
            __syncthreads();
            if (tid < 128) {
                int r = tid >> 5, b = tid & 31;
                float v = 0.f;
#pragma unroll
                for (int ww = 0; ww < 8; ww++) v += part[r * 256 + ww * 32 + b];
                v = tanhf(v);
                g_outs_bf[((size_t)tO * B_ + b) * H_ + u0 + r] = __float2bfloat16(v);
            }
        }

        if (tau != NT_ - 1) gridbar(++nbar * CTAS_);
    }
}

// ---------------- vocab GEMM: logits = outs_bf @ wlin_bf^T ------------------
// CTA tile 256x128, 512 threads (16 warps, 4m x 4n, warp tile 64x32),
// double-buffered dynamic SMEM, k-tile 32
#define WMMA_SMEM ((2 * 256 * 40 + 2 * 128 * 40) * 2)   // 61440 bytes
__global__ void __launch_bounds__(512)
k_wmma(float* __restrict__ C) {
    extern __shared__ __align__(16) __nv_bfloat16 wsm[];
    __nv_bfloat16* As = wsm;                      // [2][256*40]
    __nv_bfloat16* Bs = wsm + 2 * 256 * 40;       // [2][128*40]
    const int m0 = blockIdx.y * 256, n0 = blockIdx.x * 128;
    const int tid = threadIdx.x;
    const int wid = tid >> 5;
    const int wm = (wid >> 2) * 64, wn = (wid & 3) * 32;
    wmma::fragment<wmma::accumulator, 16, 16, 16, float> acc[4][2];
#pragma unroll
    for (int i = 0; i < 4; i++)
#pragma unroll
        for (int j = 0; j < 2; j++) wmma::fill_fragment(acc[i][j], 0.f);
    const int ar = tid >> 1, ac = (tid & 1) * 16;   // A: 2 uint4 per thread
    const int br = tid >> 2, bc = (tid & 3) * 8;    // B: 1 uint4 per thread

    // preload k-tile 0
    *reinterpret_cast<uint4*>(&As[ar * 40 + ac]) =
        *reinterpret_cast<const uint4*>(&g_outs_bf[(size_t)(m0 + ar) * D_ + ac]);
    *reinterpret_cast<uint4*>(&As[ar * 40 + ac + 8]) =
        *reinterpret_cast<const uint4*>(&g_outs_bf[(size_t)(m0 + ar) * D_ + ac + 8]);
    *reinterpret_cast<uint4*>(&Bs[br * 40 + bc]) =
        *reinterpret_cast<const uint4*>(&g_wlin_bf[(size_t)(n0 + br) * D_ + bc]);
    __syncthreads();

    int buf = 0;
    for (int k0 = 0; k0 < D_; k0 += 32) {
        uint4 ra0, ra1, rb0;
        const bool nx = (k0 + 32 < D_);
        if (nx) {
            ra0 = *reinterpret_cast<const uint4*>(&g_outs_bf[(size_t)(m0 + ar) * D_ + k0 + 32 + ac]);
            ra1 = *reinterpret_cast<const uint4*>(&g_outs_bf[(size_t)(m0 + ar) * D_ + k0 + 32 + ac + 8]);
            rb0 = *reinterpret_cast<const uint4*>(&g_wlin_bf[(size_t)(n0 + br) * D_ + k0 + 32 + bc]);
        }
        const __nv_bfloat16* Ab = As + buf * (256 * 40);
        const __nv_bfloat16* Bb = Bs + buf * (128 * 40);
#pragma unroll
        for (int sub = 0; sub < 2; sub++) {
            wmma::fragment<wmma::matrix_b, 16, 16, 16, __nv_bfloat16, wmma::col_major> bf[2];
#pragma unroll
            for (int j = 0; j < 2; j++)
                wmma::load_matrix_sync(bf[j], &Bb[(wn + j * 16) * 40 + sub * 16], 40);
#pragma unroll
            for (int i = 0; i < 4; i++) {
                wmma::fragment<wmma::matrix_a, 16, 16, 16, __nv_bfloat16, wmma::row_major> af;
                wmma::load_matrix_sync(af, &Ab[(wm + i * 16) * 40 + sub * 16], 40);
#pragma unroll
                for (int j = 0; j < 2; j++) wmma::mma_sync(acc[i][j], af, bf[j], acc[i][j]);
            }
        }
        if (nx) {
            __nv_bfloat16* Aw = As + (buf ^ 1) * (256 * 40);
            __nv_bfloat16* Bw = Bs + (buf ^ 1) * (128 * 40);
            *reinterpret_cast<uint4*>(&Aw[ar * 40 + ac]) = ra0;
            *reinterpret_cast<uint4*>(&Aw[ar * 40 + ac + 8]) = ra1;
            *reinterpret_cast<uint4*>(&Bw[br * 40 + bc]) = rb0;
        }
        __syncthreads();
        buf ^= 1;
    }
#pragma unroll
    for (int i = 0; i < 4; i++)
#pragma unroll
        for (int j = 0; j < 2; j++)
            wmma::store_matrix_sync(C + (size_t)(m0 + wm + i * 16) * V_ + n0 + wn + j * 16,
                                    acc[i][j], V_, wmma::mem_row_major);
}

// ---------------- log_softmax (adds b_lin, in-place, float4 vectorized) -----
__global__ void k_logsoftmax(float* __restrict__ logits, const float* __restrict__ b_lin) {
    const int row = blockIdx.x;
    float* p = logits + (size_t)row * V_;
    float4* p4 = reinterpret_cast<float4*>(p);
    const float4* b4 = reinterpret_cast<const float4*>(b_lin);
    const int tid = threadIdx.x;
    float m = -1e30f, s = 0.f;
    for (int v = tid; v < V_ / 4; v += 256) {
        float4 x = p4[v], bb = b4[v];
        float e[4] = {x.x + bb.x, x.y + bb.y, x.z + bb.z, x.w + bb.w};
#pragma unroll
        for (int q = 0; q < 4; q++) {
            if (e[q] > m) { s = s * __expf(m - e[q]) + 1.f; m = e[q]; }
            else          { s += __expf(e[q] - m); }
        }
    }
    __shared__ float sm[256], ss[256];
    sm[tid] = m; ss[tid] = s;
    __syncthreads();
    for (int off = 128; off; off >>= 1) {
        if (tid < off) {
            float m2 = sm[tid + off], s2 = ss[tid + off];
            float M = fmaxf(sm[tid], m2);
            ss[tid] = ss[tid] * __expf(sm[tid] - M) + s2 * __expf(m2 - M);
            sm[tid] = M;
        }
        __syncthreads();
    }
    float lse = sm[0] + logf(ss[0]);
    for (int v = tid; v < V_ / 4; v += 256) {
        float4 x = p4[v], bb = b4[v];
        x.x = x.x + bb.x - lse; x.y = x.y + bb.y - lse;
        x.z = x.z + bb.z - lse; x.w = x.w + bb.w - lse;
        p4[v] = x;
    }
}

// ---------------- host driver ----------------------------------------------
extern "C" void kernel_launch(void* const* d_in, const int* in_sizes, int n_in,
                              void* d_out, int out_size) {
    const int*   tokens     = (const int*)d_in[0];
    const float* h0         = (const float*)d_in[1];
    const float* c0         = (const float*)d_in[2];
    const float* context    = (const float*)d_in[3];
    const float* embedding  = (const float*)d_in[4];
    const float* Wih        = (const float*)d_in[5];
    const float* Whh        = (const float*)d_in[6];
    const float* bih        = (const float*)d_in[7];
    const float* bhh        = (const float*)d_in[8];
    const float* W_attn_in  = (const float*)d_in[9];
    const float* W_attn_out = (const float*)d_in[10];
    const float* W_lin      = (const float*)d_in[11];
    const float* b_lin      = (const float*)d_in[12];
    float* out = (float*)d_out;

    cudaFuncSetAttribute(k_scan, cudaFuncAttributeMaxDynamicSharedMemorySize, SMEM_BYTES);
    cudaFuncSetAttribute(k_wmma, cudaFuncAttributeMaxDynamicSharedMemorySize, WMMA_SMEM);

    const float* Wih1 = Wih + (size_t)G4_ * D_;
    const float* Whh1 = Whh + (size_t)G4_ * H_;

    k_reset<<<1, 1>>>();
    k_convert_wlin<<<(V_ * D_ / 4 + 255) / 256, 256>>>(W_lin);
    k_gemm_pre<<<dim3(G4_ / 128, MR_ / 128), 256>>>(tokens, embedding, Wih, bih, bhh);
    k_c2<<<dim3(H_ / 128, (B_ * S_) / 128), 256>>>(context, W_attn_in);
    k_scan<<<CTAS_, 256, SMEM_BYTES>>>(Whh, Wih1, Whh1, bih, bhh, context,
                                       W_attn_out, h0, c0, out);
    k_wmma<<<dim3(V_ / 128, MR_ / 256), 512, WMMA_SMEM>>>(out);
    k_logsoftmax<<<MR_, 256>>>(out, b_lin);
}

// round 14
// speedup vs baseline: 1.5162x; 1.0085x over previous
#include <cuda_runtime.h>
#include <cuda_bf16.h>
#include <mma.h>
using namespace nvcuda;

#define B_  32
#define T_  64
#define S_  64
#define H_  512
#define D_  512
#define V_  32000
#define G4_ 2048            // 4*H
#define MR_ 2048            // T*B rows

#define CTAS_ 128
#define UPC_  4             // units per CTA (both layers)
#define NT_   67            // pipelined ticks = T + 3

// d_out layout (f32): log_probs [T,B,V], hT [2,B,H], cT [2,B,H], attn [B,S]
#define OFF_HT   ((size_t)T_ * B_ * V_)
#define OFF_CT   (OFF_HT + (size_t)2 * B_ * H_)
#define OFF_ATTN (OFF_CT + (size_t)2 * B_ * H_)

// ---------------- device scratch -------------------------------------------
__device__ float g_pre0[(size_t)T_ * G4_ * B_];       // [t][gate_row][b]  16MB
__device__ float g_c2[(size_t)B_ * S_ * H_];          // context @ W_attn_in 4MB
__device__ float g_h0[2][B_ * H_];                    // h layer0, [b][k] row-major
__device__ float g_h1[2][B_ * H_];                    // h layer1, [b][k] row-major
__device__ float4 g_cat4[2][(2 * H_ / 4) * B_];       // [slot][h-quad][b] k4 layout
__device__ __nv_bfloat16 g_outs_bf[(size_t)MR_ * H_];
__device__ __nv_bfloat16 g_wlin_bf[(size_t)V_ * D_];
__device__ unsigned g_bar;

__device__ __forceinline__ float sigf(float x) { return 1.f / (1.f + __expf(-x)); }
__device__ __forceinline__ float totf(float x) { return wmma::__float_to_tf32(x); }

__global__ void k_reset() { g_bar = 0u; }

// ---------------- W_lin fp32 -> bf16 ---------------------------------------
__global__ void k_convert_wlin(const float* __restrict__ w) {
    int i = blockIdx.x * blockDim.x + threadIdx.x;
    if (i < (V_ * D_) / 4) {
        float4 v = reinterpret_cast<const float4*>(w)[i];
        __nv_bfloat162* o = reinterpret_cast<__nv_bfloat162*>(g_wlin_bf);
        o[i * 2]     = __floats2bfloat162_rn(v.x, v.y);
        o[i * 2 + 1] = __floats2bfloat162_rn(v.z, v.w);
    }
}

// ---------------- embed + input projection (tf32 WMMA) ----------------------
__global__ void __launch_bounds__(256)
k_gemm_pre(const int* __restrict__ tokens,
           const float* __restrict__ embedding,
           const float* __restrict__ Wih0,
           const float* __restrict__ bih0,
           const float* __restrict__ bhh0) {
    __shared__ float As[128 * 36];
    __shared__ float Bs[128 * 36];
    __shared__ float scr[8 * 320];
    __shared__ float bsh[128];
    __shared__ int   toks[128];
    const int tid = threadIdx.x;
    const int w   = tid >> 5;
    const int lane = tid & 31;
    const int m0 = blockIdx.y * 128, n0 = blockIdx.x * 128;
    const int wm = (w >> 2) * 64, wn = (w & 3) * 32;

    if (tid < 128) {
        int m = m0 + tid;
        toks[tid] = tokens[(m & 31) * T_ + (m >> 5)];
        bsh[tid] = bih0[n0 + tid] + bhh0[n0 + tid];
    }
    __syncthreads();

    wmma::fragment<wmma::accumulator, 16, 16, 8, float> acc[4][2];
#pragma unroll
    for (int i = 0; i < 4; i++)
#pragma unroll
        for (int j = 0; j < 2; j++) wmma::fill_fragment(acc[i][j], 0.f);

    for (int k0 = 0; k0 < D_; k0 += 32) {
#pragma unroll
        for (int it = 0; it < 4; it++) {
            int idx = tid + it * 256;
            int r = idx >> 3, c = (idx & 7) * 4;
            float4 va = *reinterpret_cast<const float4*>(
                embedding + (size_t)toks[r] * D_ + k0 + c);
            As[r * 36 + c] = totf(va.x); As[r * 36 + c + 1] = totf(va.y);
            As[r * 36 + c + 2] = totf(va.z); As[r * 36 + c + 3] = totf(va.w);
            float4 vb = *reinterpret_cast<const float4*>(
                Wih0 + (size_t)(n0 + r) * D_ + k0 + c);
            Bs[r * 36 + c] = totf(vb.x); Bs[r * 36 + c + 1] = totf(vb.y);
            Bs[r * 36 + c + 2] = totf(vb.z); Bs[r * 36 + c + 3] = totf(vb.w);
        }
        __syncthreads();
#pragma unroll
        for (int kk = 0; kk < 4; kk++) {
            wmma::fragment<wmma::matrix_b, 16, 16, 8, wmma::precision::tf32, wmma::col_major> b[2];
#pragma unroll
            for (int j = 0; j < 2; j++)
                wmma::load_matrix_sync(b[j], Bs + (wn + j * 16) * 36 + kk * 8, 36);
#pragma unroll
            for (int i = 0; i < 4; i++) {
                wmma::fragment<wmma::matrix_a, 16, 16, 8, wmma::precision::tf32, wmma::row_major> a;
                wmma::load_matrix_sync(a, As + (wm + i * 16) * 36 + kk * 8, 36);
#pragma unroll
                for (int j = 0; j < 2; j++) wmma::mma_sync(acc[i][j], a, b[j], acc[i][j]);
            }
        }
        __syncthreads();
    }
#pragma unroll
    for (int i = 0; i < 4; i++)
#pragma unroll
        for (int j = 0; j < 2; j++) {
            wmma::store_matrix_sync(scr + w * 320, acc[i][j], 20, wmma::mem_row_major);
            __syncwarp();
            int c = lane >> 1;
            int r0 = (lane & 1) * 8;
            int n = n0 + wn + j * 16 + c;
            int mbase = m0 + wm + i * 16 + r0;
            int t = mbase >> 5, b0 = mbase & 31;
            float bias = bsh[wn + j * 16 + c];
            float* dst = g_pre0 + ((size_t)t * G4_ + n) * B_ + b0;
#pragma unroll
            for (int rr = 0; rr < 8; rr++)
                dst[rr] = scr[w * 320 + (r0 + rr) * 20 + c] + bias;
            __syncwarp();
        }
}

// ---------------- C2 = context @ W_attn_in (tf32 WMMA) ----------------------
__global__ void __launch_bounds__(256)
k_c2(const float* __restrict__ A, const float* __restrict__ Wq) {
    __shared__ float As[128 * 36];
    __shared__ float Bs[32 * 132];
    const int tid = threadIdx.x;
    const int w   = tid >> 5;
    const int m0 = blockIdx.y * 128, n0 = blockIdx.x * 128;
    const int wm = (w >> 2) * 64, wn = (w & 3) * 32;

    wmma::fragment<wmma::accumulator, 16, 16, 8, float> acc[4][2];
#pragma unroll
    for (int i = 0; i < 4; i++)
#pragma unroll
        for (int j = 0; j < 2; j++) wmma::fill_fragment(acc[i][j], 0.f);

    for (int k0 = 0; k0 < H_; k0 += 32) {
#pragma unroll
        for (int it = 0; it < 4; it++) {
            int idx = tid + it * 256;
            int r = idx >> 3, c = (idx & 7) * 4;
            float4 va = *reinterpret_cast<const float4*>(
                A + (size_t)(m0 + r) * H_ + k0 + c);
            As[r * 36 + c] = totf(va.x); As[r * 36 + c + 1] = totf(va.y);
            As[r * 36 + c + 2] = totf(va.z); As[r * 36 + c + 3] = totf(va.w);
        }
#pragma unroll
        for (int it = 0; it < 4; it++) {
            int idx = tid + it * 256;
            int r = idx >> 5, c = (idx & 31) * 4;
            float4 vb = *reinterpret_cast<const float4*>(
                Wq + (size_t)(k0 + r) * H_ + n0 + c);
            Bs[r * 132 + c] = totf(vb.x); Bs[r * 132 + c + 1] = totf(vb.y);
            Bs[r * 132 + c + 2] = totf(vb.z); Bs[r * 132 + c + 3] = totf(vb.w);
        }
        __syncthreads();
#pragma unroll
        for (int kk = 0; kk < 4; kk++) {
            wmma::fragment<wmma::matrix_b, 16, 16, 8, wmma::precision::tf32, wmma::row_major> b[2];
#pragma unroll
            for (int j = 0; j < 2; j++)
                wmma::load_matrix_sync(b[j], Bs + kk * 8 * 132 + wn + j * 16, 132);
#pragma unroll
            for (int i = 0; i < 4; i++) {
                wmma::fragment<wmma::matrix_a, 16, 16, 8, wmma::precision::tf32, wmma::row_major> a;
                wmma::load_matrix_sync(a, As + (wm + i * 16) * 36 + kk * 8, 36);
#pragma unroll
                for (int j = 0; j < 2; j++) wmma::mma_sync(acc[i][j], a, b[j], acc[i][j]);
            }
        }
        __syncthreads();
    }
#pragma unroll
    for (int i = 0; i < 4; i++)
#pragma unroll
        for (int j = 0; j < 2; j++)
            wmma::store_matrix_sync(g_c2 + (size_t)(m0 + wm + i * 16) * H_ + n0 + wn + j * 16,
                                    acc[i][j], H_, wmma::mem_row_major);
}

// ---------------- pipelined persistent scan kernel ---------------------------
// SMEM float offsets
#define SM_W0    0                          // 16 x 520
#define SM_W1    8320                       // 16 x 1040
#define SM_WOS   24960                      // 4 x 1024
#define SM_STAGE 29056                      // 32 x 520
#define SM_PBUF0 45696                      // 8 x 256
#define SM_PBUF1 47744                      // 8 x 256
#define SM_CB    49792                      // 2 x 4 x 32
#define SM_B1    50048                      // 16
#define SM_PART  50064                      // 4 x 8 x 32 = 1024
#define SM_SC    51088                      // 64
#define SM_ATT   51152                      // 64
#define SMEM_FLOATS 51216
#define SMEM_BYTES  (SMEM_FLOATS * 4)

#define LDW0  520
#define LDW1  1040
#define LDST  520

__device__ __forceinline__ void gridbar(unsigned target) {
    __threadfence();
    __syncthreads();
    if (threadIdx.x == 0) {
        atomicAdd(&g_bar, 1u);
        volatile unsigned* vb = &g_bar;
        while (*vb < target) __nanosleep(32);
    }
    __syncthreads();
}

// copy 32x512 row-major h into padded stage [b][520], rounding to tf32
__device__ __forceinline__ void stage_rows(float* stg, const float4* src, int tid) {
    for (int idx = tid; idx < 4096; idx += 256) {
        int b = idx >> 7, j = idx & 127;
        float4 v = __ldcg(&src[idx]);
        v.x = totf(v.x); v.y = totf(v.y); v.z = totf(v.z); v.w = totf(v.w);
        reinterpret_cast<float4*>(stg + b * LDST)[j] = v;
    }
}

__global__ void __launch_bounds__(256, 1)
k_scan(const float* __restrict__ Whh0, const float* __restrict__ Wih1,
       const float* __restrict__ Whh1, const float* __restrict__ bih,
       const float* __restrict__ bhh, const float* __restrict__ context,
       const float* __restrict__ Wout, const float* __restrict__ h0in,
       const float* __restrict__ c0in, float* __restrict__ out) {
    extern __shared__ float sm[];
    float*  W0s   = sm + SM_W0;
    float*  W1s   = sm + SM_W1;
    float*  Wos   = sm + SM_WOS;
    float*  stg   = sm + SM_STAGE;
    float*  pbuf0 = sm + SM_PBUF0;
    float*  pbuf1 = sm + SM_PBUF1;
    float*  cb    = sm + SM_CB;
    float*  bias1 = sm + SM_B1;
    float*  part  = sm + SM_PART;
    float*  sc    = sm + SM_SC;
    float*  att   = sm + SM_ATT;

    const int cta = blockIdx.x;
    const int tid = threadIdx.x;
    const int w   = tid >> 5;
    const int lane = tid & 31;
    const int u0  = cta * UPC_;
    const int wn  = w & 1;            // n-tile (batch 16s)
    const int wkc = w >> 1;           // k-chunk (128s)
    const int ab  = cta & 31;         // attention batch
    const int aq  = cta >> 5;         // attention quarter (0..3)

    // -------- prologue: weights -> SMEM (pre-rounded to tf32) --------------
    for (int idx = tid; idx < 16 * 128; idx += 256) {
        int r = idx >> 7, kq = idx & 127;
        int row = ((r >> 2) * H_) + u0 + (r & 3);
        float4 v = *reinterpret_cast<const float4*>(Whh0 + (size_t)row * H_ + kq * 4);
        v.x = totf(v.x); v.y = totf(v.y); v.z = totf(v.z); v.w = totf(v.w);
        reinterpret_cast<float4*>(W0s + r * LDW0)[kq] = v;
    }
    for (int idx = tid; idx < 16 * 256; idx += 256) {
        int r = idx >> 8, kq = idx & 255;
        int row = ((r >> 2) * H_) + u0 + (r & 3);
        const float* src = (kq < 128)
            ? (Wih1 + (size_t)row * H_ + kq * 4)
            : (Whh1 + (size_t)row * H_ + (kq - 128) * 4);
        float4 v = *reinterpret_cast<const float4*>(src);
        v.x = totf(v.x); v.y = totf(v.y); v.z = totf(v.z); v.w = totf(v.w);
        reinterpret_cast<float4*>(W1s + r * LDW1)[kq] = v;
    }
    for (int idx = tid; idx < 4 * 256; idx += 256) {     // Wos fp32
        int r = idx >> 8, kq = idx & 255;
        reinterpret_cast<float4*>(Wos + r * 1024)[kq] =
            *reinterpret_cast<const float4*>(Wout + (size_t)(u0 + r) * (2 * H_) + kq * 4);
    }
    if (tid < 16) {
        int row = ((tid >> 2) * H_) + u0 + (tid & 3);
        bias1[tid] = bih[G4_ + row] + bhh[G4_ + row];
    }
    {   // cell state: cb[l*128 + ul*32 + b]
        int l = tid >> 7, ul = (tid >> 5) & 3, b = tid & 31;
        cb[tid] = c0in[(size_t)l * B_ * H_ + (size_t)b * H_ + u0 + ul];
    }
    if (tid < 32) {   // initial h -> slot 1 (read at tick 0 / tick 1)
        int b = tid;
#pragma unroll
        for (int ul = 0; ul < 4; ul++) {
            __stcg(&g_h0[1][b * H_ + u0 + ul], h0in[(size_t)b * H_ + u0 + ul]);
            __stcg(&g_h1[1][b * H_ + u0 + ul], h0in[(size_t)B_ * H_ + b * H_ + u0 + ul]);
        }
    }
    unsigned nbar = 0;
    gridbar(++nbar * CTAS_);

    // -------- pipelined main loop: tick tau computes
    //          L0(t=tau), L1(t=tau-1), attn(t=tau-2), attnout(t=tau-3) -------
    for (int tau = 0; tau < NT_; tau++) {
        const int sh0r = (tau + 1) & 1, sh0w = tau & 1;
        const int sh1r = tau & 1,       sh1w = (tau + 1) & 1;
        const int catw = tau & 1,       catr = (tau + 1) & 1;

        // (a) stage h0out_{tau-1}; prefetch h1out_{tau-2} into registers;
        //     prefetch pre0 gate values for the L0 epilogue
        stage_rows(stg, reinterpret_cast<const float4*>(g_h0[sh0r]), tid);
        float4 pf[16];
        {
            const float4* h1src = reinterpret_cast<const float4*>(g_h1[sh1r]);
#pragma unroll
            for (int q = 0; q < 16; q++) pf[q] = __ldcg(&h1src[tid + q * 256]);
        }
        float preI = 0.f, preF = 0.f, preG = 0.f, preO = 0.f;
        if (tau <= 63 && tid < 128) {
            int ul = tid >> 5, b = tid & 31, u = u0 + ul;
            const float* pre = g_pre0 + (size_t)tau * G4_ * B_;
            preI = __ldg(&pre[((size_t)0 * H_ + u) * B_ + b]);
            preF = __ldg(&pre[((size_t)1 * H_ + u) * B_ + b]);
            preG = __ldg(&pre[((size_t)2 * H_ + u) * B_ + b]);
            preO = __ldg(&pre[((size_t)3 * H_ + u) * B_ + b]);
        }
        __syncthreads();

        // (b) L0 mma (acc0) + L1 pass0 mma (acc1) off the same stage
        wmma::fragment<wmma::accumulator, 16, 16, 8, float> acc0, acc1;
        wmma::fill_fragment(acc0, 0.f);
        wmma::fill_fragment(acc1, 0.f);
#pragma unroll
        for (int kk = 0; kk < 16; kk++) {
            int k = wkc * 128 + kk * 8;
            wmma::fragment<wmma::matrix_b, 16, 16, 8, wmma::precision::tf32, wmma::col_major> b;
            wmma::load_matrix_sync(b, stg + (wn * 16) * LDST + k, LDST);
            wmma::fragment<wmma::matrix_a, 16, 16, 8, wmma::precision::tf32, wmma::row_major> a0, a1;
            wmma::load_matrix_sync(a0, W0s + k, LDW0);
            wmma::load_matrix_sync(a1, W1s + k, LDW1);
            wmma::mma_sync(acc0, a0, b, acc0);
            wmma::mma_sync(acc1, a1, b, acc1);
        }
        __syncthreads();   // done reading stage

        // (c) write prefetched h1 into stage (pure STS)
#pragma unroll
        for (int q = 0; q < 16; q++) {
            int idx = tid + q * 256;
            float4 v = pf[q];
            v.x = totf(v.x); v.y = totf(v.y); v.z = totf(v.z); v.w = totf(v.w);
            reinterpret_cast<float4*>(stg + (idx >> 7) * LDST)[idx & 127] = v;
        }
        __syncthreads();

        // (d) L1 pass1 mma
#pragma unroll
        for (int kk = 0; kk < 16; kk++) {
            int k = wkc * 128 + kk * 8;
            wmma::fragment<wmma::matrix_b, 16, 16, 8, wmma::precision::tf32, wmma::col_major> b;
            wmma::load_matrix_sync(b, stg + (wn * 16) * LDST + k, LDST);
            wmma::fragment<wmma::matrix_a, 16, 16, 8, wmma::precision::tf32, wmma::row_major> a;
            wmma::load_matrix_sync(a, W1s + 512 + k, LDW1);
            wmma::mma_sync(acc1, a, b, acc1);
        }
        wmma::store_matrix_sync(pbuf0 + w * 256, acc0, 16, wmma::mem_row_major);
        wmma::store_matrix_sync(pbuf1 + w * 256, acc1, 16, wmma::mem_row_major);
        __syncthreads();

        // (f) fused reduction+epilogue: L0 on tid<128, L1 on tid>=128
        if (tau <= 63 && tid < 128) {
            int t = tau;
            int ul = tid >> 5, b = tid & 31, u = u0 + ul;
            const int bo = (b >> 4) * 256 + (b & 15);
            float s[4];
#pragma unroll
            for (int g = 0; g < 4; g++) {
                float v = 0.f;
#pragma unroll
                for (int kc = 0; kc < 4; kc++)
                    v += pbuf0[bo + kc * 512 + (g * 4 + ul) * 16];
                s[g] = v;
            }
            float gi = sigf(s[0] + preI);
            float gf = sigf(s[1] + preF);
            float gg = tanhf(s[2] + preG);
            float go = sigf(s[3] + preO);
            float c = gf * cb[ul * 32 + b] + gi * gg;
            cb[ul * 32 + b] = c;
            float h = go * tanhf(c);
            __stcg(&g_h0[sh0w][b * H_ + u], h);
            if (t == T_ - 1) {
                out[OFF_HT + (size_t)b * H_ + u] = h;
                out[OFF_CT + (size_t)b * H_ + u] = c;
            }
        }
        if (tau >= 1 && tau <= 64 && tid >= 128) {
            int t = tau - 1;
            int tt = tid - 128;
            int ul = tt >> 5, b = tt & 31, u = u0 + ul;
            const int bo = (b >> 4) * 256 + (b & 15);
            float s[4];
#pragma unroll
            for (int g = 0; g < 4; g++) {
                float v = 0.f;
#pragma unroll
                for (int kc = 0; kc < 4; kc++)
                    v += pbuf1[bo + kc * 512 + (g * 4 + ul) * 16];
                s[g] = v;
            }
            float gi = sigf(s[0] + bias1[0  + ul]);
            float gf = sigf(s[1] + bias1[4  + ul]);
            float gg = tanhf(s[2] + bias1[8  + ul]);
            float go = sigf(s[3] + bias1[12 + ul]);
            float c = gf * cb[128 + ul * 32 + b] + gi * gg;
            cb[128 + ul * 32 + b] = c;
            float h = go * tanhf(c);
            __stcg(&g_h1[sh1w][b * H_ + u], h);
            if (t == T_ - 1) {
                out[OFF_HT + (size_t)B_ * H_ + (size_t)b * H_ + u] = h;
                out[OFF_CT + (size_t)B_ * H_ + (size_t)b * H_ + u] = c;
            }
        }

        // (g) attention for t = tau-2 (stg holds h1out_{tau-2})
        if (tau >= 2 && tau <= 65) {
            const float4* qs4 = reinterpret_cast<const float4*>(stg + ab * LDST);
#pragma unroll
            for (int si = 0; si < 8; si++) {
                int s = w * 8 + si;
                const float4* c2r = reinterpret_cast<const float4*>(
                    g_c2 + (size_t)(ab * S_ + s) * H_);
                float a = 0.f;
#pragma unroll
                for (int kq = lane; kq < 128; kq += 32) {
                    float4 cv = __ldg(&c2r[kq]);
                    float4 qv = qs4[kq];
                    a += cv.x * qv.x + cv.y * qv.y + cv.z * qv.z + cv.w * qv.w;
                }
#pragma unroll
                for (int off = 16; off; off >>= 1) a += __shfl_xor_sync(0xffffffffu, a, off);
                if (lane == 0) sc[s] = a;
            }
            __syncthreads();
            if (tid < 32) {
                float v0 = sc[tid], v1 = sc[tid + 32];
                float m = fmaxf(v0, v1);
#pragma unroll
                for (int off = 16; off; off >>= 1) m = fmaxf(m, __shfl_xor_sync(0xffffffffu, m, off));
                float e0 = __expf(v0 - m), e1 = __expf(v1 - m);
                float s2 = e0 + e1;
#pragma unroll
                for (int off = 16; off; off >>= 1) s2 += __shfl_xor_sync(0xffffffffu, s2, off);
                float inv = 1.f / s2;
                att[tid] = e0 * inv; att[tid + 32] = e1 * inv;
                if (aq == 0 && tau == 65) {
                    out[OFF_ATTN + ab * S_ + tid]      = e0 * inv;
                    out[OFF_ATTN + ab * S_ + tid + 32] = e1 * inv;
                }
            }
            __syncthreads();
            {   // ctx: quarter handles h in [aq*128, aq*128+128); 2 threads per h
                int h = aq * 128 + (tid >> 1);
                int s0 = (tid & 1) * 32;
                const float* cx = context + (size_t)ab * S_ * H_ + h;
                float a = 0.f;
#pragma unroll 8
                for (int s = s0; s < s0 + 32; s++) a += att[s] * cx[(size_t)s * H_];
                a += __shfl_xor_sync(0xffffffffu, a, 1);
                if ((tid & 1) == 0) {
                    float* catp = reinterpret_cast<float*>(g_cat4[catw]);
                    __stcg(&catp[((h >> 2) * 32 + ab) * 4 + (h & 3)], a);
                    int h2 = H_ + h;
                    float hv = __ldcg(&g_h1[sh1r][ab * H_ + h]);
                    __stcg(&catp[((h2 >> 2) * 32 + ab) * 4 + (h2 & 3)], hv);
                }
            }
        }

        // (h) attention-out for t = tau-3: warp w owns k-quads [w*16, w*16+16)
        if (tau >= 3) {
            const int tO = tau - 3;
            float racc[4] = {0.f, 0.f, 0.f, 0.f};
            const int i0 = w * 16;
#pragma unroll
            for (int half = 0; half < 2; half++) {
                const float4* catp = g_cat4[catr] + half * 4096;
                const float4* wr = reinterpret_cast<const float4*>(Wos + half * H_);
#pragma unroll 4
                for (int i = 0; i < 16; i++) {
                    float4 h = __ldcg(&catp[(i0 + i) * 32 + lane]);
#pragma unroll
                    for (int row = 0; row < 4; row++) {
                        float4 x = wr[row * 256 + i0 + i];
                        racc[row] += x.x * h.x + x.y * h.y + x.z * h.z + x.w * h.w;
                    }
                }
            }
#pragma unroll
            for (int row = 0; row < 4; row++)
                part[row * 256 + w * 32 + lane] = racc[row];
            __syncthreads();
            if (tid < 128) {
                int r = tid >> 5, b = tid & 31;
                float v = 0.f;
#pragma unroll
                for (int ww = 0; ww < 8; ww++) v += part[r * 256 + ww * 32 + b];
                v = tanhf(v);
                g_outs_bf[((size_t)tO * B_ + b) * H_ + u0 + r] = __float2bfloat16(v);
            }
        }

        if (tau != NT_ - 1) gridbar(++nbar * CTAS_);
    }
}

// ---------------- vocab GEMM: logits = outs_bf @ wlin_bf^T ------------------
// CTA tile 256x128, 512 threads (16 warps, 4m x 4n, warp tile 64x32),
// double-buffered dynamic SMEM, k-tile 64
#define WMMA_SMEM ((2 * 256 * 72 + 2 * 128 * 72) * 2)   // 110592 bytes
__global__ void __launch_bounds__(512)
k_wmma(float* __restrict__ C) {
    extern __shared__ __align__(16) __nv_bfloat16 wsm[];
    __nv_bfloat16* As = wsm;                      // [2][256*72]
    __nv_bfloat16* Bs = wsm + 2 * 256 * 72;       // [2][128*72]
    const int m0 = blockIdx.y * 256, n0 = blockIdx.x * 128;
    const int tid = threadIdx.x;
    const int wid = tid >> 5;
    const int wm = (wid >> 2) * 64, wn = (wid & 3) * 32;
    wmma::fragment<wmma::accumulator, 16, 16, 16, float> acc[4][2];
#pragma unroll
    for (int i = 0; i < 4; i++)
#pragma unroll
        for (int j = 0; j < 2; j++) wmma::fill_fragment(acc[i][j], 0.f);
    const int ar = tid >> 1, ac = (tid & 1) * 32;   // A: 4 uint4 per thread
    const int br = tid >> 2, bc = (tid & 3) * 16;   // B: 2 uint4 per thread

    // preload k-tile 0
#pragma unroll
    for (int q = 0; q < 4; q++)
        *reinterpret_cast<uint4*>(&As[ar * 72 + ac + q * 8]) =
            *reinterpret_cast<const uint4*>(&g_outs_bf[(size_t)(m0 + ar) * D_ + ac + q * 8]);
#pragma unroll
    for (int q = 0; q < 2; q++)
        *reinterpret_cast<uint4*>(&Bs[br * 72 + bc + q * 8]) =
            *reinterpret_cast<const uint4*>(&g_wlin_bf[(size_t)(n0 + br) * D_ + bc + q * 8]);
    __syncthreads();

    int buf = 0;
    for (int k0 = 0; k0 < D_; k0 += 64) {
        uint4 ra[4], rb[2];
        const bool nx = (k0 + 64 < D_);
        if (nx) {
#pragma unroll
            for (int q = 0; q < 4; q++)
                ra[q] = *reinterpret_cast<const uint4*>(
                    &g_outs_bf[(size_t)(m0 + ar) * D_ + k0 + 64 + ac + q * 8]);
#pragma unroll
            for (int q = 0; q < 2; q++)
                rb[q] = *reinterpret_cast<const uint4*>(
                    &g_wlin_bf[(size_t)(n0 + br) * D_ + k0 + 64 + bc + q * 8]);
        }
        const __nv_bfloat16* Ab = As + buf * (256 * 72);
        const __nv_bfloat16* Bb = Bs + buf * (128 * 72);
#pragma unroll
        for (int sub = 0; sub < 4; sub++) {
            wmma::fragment<wmma::matrix_b, 16, 16, 16, __nv_bfloat16, wmma::col_major> bf[2];
#pragma unroll
            for (int j = 0; j < 2; j++)
                wmma::load_matrix_sync(bf[j], &Bb[(wn + j * 16) * 72 + sub * 16], 72);
#pragma unroll
            for (int i = 0; i < 4; i++) {
                wmma::fragment<wmma::matrix_a, 16, 16, 16, __nv_bfloat16, wmma::row_major> af;
                wmma::load_matrix_sync(af, &Ab[(wm + i * 16) * 72 + sub * 16], 72);
#pragma unroll
                for (int j = 0; j < 2; j++) wmma::mma_sync(acc[i][j], af, bf[j], acc[i][j]);
            }
        }
        if (nx) {
            __nv_bfloat16* Aw = As + (buf ^ 1) * (256 * 72);
            __nv_bfloat16* Bw = Bs + (buf ^ 1) * (128 * 72);
#pragma unroll
            for (int q = 0; q < 4; q++)
                *reinterpret_cast<uint4*>(&Aw[ar * 72 + ac + q * 8]) = ra[q];
#pragma unroll
            for (int q = 0; q < 2; q++)
                *reinterpret_cast<uint4*>(&Bw[br * 72 + bc + q * 8]) = rb[q];
        }
        __syncthreads();
        buf ^= 1;
    }
#pragma unroll
    for (int i = 0; i < 4; i++)
#pragma unroll
        for (int j = 0; j < 2; j++)
            wmma::store_matrix_sync(C + (size_t)(m0 + wm + i * 16) * V_ + n0 + wn + j * 16,
                                    acc[i][j], V_, wmma::mem_row_major);
}

// ---------------- log_softmax (adds b_lin, in-place; no-max: logits bounded) -
__global__ void k_logsoftmax(float* __restrict__ logits, const float* __restrict__ b_lin) {
    const int row = blockIdx.x;
    float* p = logits + (size_t)row * V_;
    float4* p4 = reinterpret_cast<float4*>(p);
    const float4* b4 = reinterpret_cast<const float4*>(b_lin);
    const int tid = threadIdx.x;
    float s = 0.f;
    for (int v = tid; v < V_ / 4; v += 256) {
        float4 x = p4[v], bb = b4[v];
        s += __expf(x.x + bb.x) + __expf(x.y + bb.y)
           + __expf(x.z + bb.z) + __expf(x.w + bb.w);
    }
    __shared__ float ss[256];
    ss[tid] = s;
    __syncthreads();
    for (int off = 128; off; off >>= 1) {
        if (tid < off) ss[tid] += ss[tid + off];
        __syncthreads();
    }
    float lse = logf(ss[0]);
    for (int v = tid; v < V_ / 4; v += 256) {
        float4 x = p4[v], bb = b4[v];
        x.x = x.x + bb.x - lse; x.y = x.y + bb.y - lse;
        x.z = x.z + bb.z - lse; x.w = x.w + bb.w - lse;
        p4[v] = x;
    }
}

// ---------------- host driver ----------------------------------------------
extern "C" void kernel_launch(void* const* d_in, const int* in_sizes, int n_in,
                              void* d_out, int out_size) {
    const int*   tokens     = (const int*)d_in[0];
    const float* h0         = (const float*)d_in[1];
    const float* c0         = (const float*)d_in[2];
    const float* context    = (const float*)d_in[3];
    const float* embedding  = (const float*)d_in[4];
    const float* Wih        = (const float*)d_in[5];
    const float* Whh        = (const float*)d_in[6];
    const float* bih        = (const float*)d_in[7];
    const float* bhh        = (const float*)d_in[8];
    const float* W_attn_in  = (const float*)d_in[9];
    const float* W_attn_out = (const float*)d_in[10];
    const float* W_lin      = (const float*)d_in[11];
    const float* b_lin      = (const float*)d_in[12];
    float* out = (float*)d_out;

    cudaFuncSetAttribute(k_scan, cudaFuncAttributeMaxDynamicSharedMemorySize, SMEM_BYTES);
    cudaFuncSetAttribute(k_wmma, cudaFuncAttributeMaxDynamicSharedMemorySize, WMMA_SMEM);

    const float* Wih1 = Wih + (size_t)G4_ * D_;
    const float* Whh1 = Whh + (size_t)G4_ * H_;

    k_reset<<<1, 1>>>();
    k_convert_wlin<<<(V_ * D_ / 4 + 255) / 256, 256>>>(W_lin);
    k_gemm_pre<<<dim3(G4_ / 128, MR_ / 128), 256>>>(tokens, embedding, Wih, bih, bhh);
    k_c2<<<dim3(H_ / 128, (B_ * S_) / 128), 256>>>(context, W_attn_in);
    k_scan<<<CTAS_, 256, SMEM_BYTES>>>(Whh, Wih1, Whh1, bih, bhh, context,
                                       W_attn_out, h0, c0, out);
    k_wmma<<<dim3(V_ / 128, MR_ / 256), 512, WMMA_SMEM>>>(out);
    k_logsoftmax<<<MR_, 256>>>(out, b_lin);
}

// round 15
// speedup vs baseline: 1.5173x; 1.0007x over previous
#include <cuda_runtime.h>
#include <cuda_bf16.h>
#include <mma.h>
using namespace nvcuda;

#define B_  32
#define T_  64
#define S_  64
#define H_  512
#define D_  512
#define V_  32000
#define G4_ 2048            // 4*H
#define MR_ 2048            // T*B rows

#define CTAS_ 128
#define UPC_  4             // units per CTA (both layers)
#define NT_   67            // pipelined ticks = T + 3

// d_out layout (f32): log_probs [T,B,V], hT [2,B,H], cT [2,B,H], attn [B,S]
#define OFF_HT   ((size_t)T_ * B_ * V_)
#define OFF_CT   (OFF_HT + (size_t)2 * B_ * H_)
#define OFF_ATTN (OFF_CT + (size_t)2 * B_ * H_)

// ---------------- device scratch -------------------------------------------
__device__ float g_pre0[(size_t)T_ * G4_ * B_];       // [t][gate_row][b]  16MB
__device__ float g_c2[(size_t)B_ * S_ * H_];          // context @ W_attn_in 4MB
__device__ float g_h0[2][B_ * H_];                    // h layer0, [b][k] row-major
__device__ float g_h1[2][B_ * H_];                    // h layer1, [b][k] row-major
__device__ float4 g_cat4[2][(2 * H_ / 4) * B_];       // [slot][h-quad][b] k4 layout
__device__ __nv_bfloat16 g_outs_bf[(size_t)MR_ * H_];
__device__ __nv_bfloat16 g_wlin_bf[(size_t)V_ * D_];
__device__ float g_rowsum[MR_];
__device__ unsigned g_bar;

__device__ __forceinline__ float sigf(float x) { return 1.f / (1.f + __expf(-x)); }
__device__ __forceinline__ float totf(float x) { return wmma::__float_to_tf32(x); }

// ---------------- W_lin fp32 -> bf16 (+ reset of bar / rowsums) -------------
__global__ void k_convert_wlin(const float* __restrict__ w) {
    if (blockIdx.x == 0) {
        if (threadIdx.x == 0) g_bar = 0u;
        for (int r = threadIdx.x; r < MR_; r += 256) g_rowsum[r] = 0.f;
    }
    int i = blockIdx.x * blockDim.x + threadIdx.x;
    if (i < (V_ * D_) / 4) {
        float4 v = reinterpret_cast<const float4*>(w)[i];
        __nv_bfloat162* o = reinterpret_cast<__nv_bfloat162*>(g_wlin_bf);
        o[i * 2]     = __floats2bfloat162_rn(v.x, v.y);
        o[i * 2 + 1] = __floats2bfloat162_rn(v.z, v.w);
    }
}

// ---------------- merged prologue: gemm_pre (CTAs 0..255) + c2 (256..319) ---
#define PRE_SMEM 48128
__global__ void __launch_bounds__(256)
k_prolog(const int* __restrict__ tokens,
         const float* __restrict__ embedding,
         const float* __restrict__ Wih0,
         const float* __restrict__ bih0,
         const float* __restrict__ bhh0,
         const float* __restrict__ ctx,
         const float* __restrict__ Wq) {
    extern __shared__ float dsm[];
    const int tid = threadIdx.x;
    const int w   = tid >> 5;
    const int lane = tid & 31;

    if (blockIdx.x < 256) {
        // ===== pre0 = emb @ Wih0^T + b, tile m128 x n128 x k32 =====
        float* As  = dsm;                 // 128*36
        float* Bs  = dsm + 4608;          // 128*36
        float* scr = dsm + 9216;          // 8*320
        float* bsh = dsm + 11776;         // 128
        int*   toks = reinterpret_cast<int*>(dsm + 11904);   // 128
        const int m0 = (blockIdx.x >> 4) * 128, n0 = (blockIdx.x & 15) * 128;
        const int wm = (w >> 2) * 64, wn = (w & 3) * 32;

        if (tid < 128) {
            int m = m0 + tid;
            toks[tid] = tokens[(m & 31) * T_ + (m >> 5)];
            bsh[tid] = bih0[n0 + tid] + bhh0[n0 + tid];
        }
        __syncthreads();

        wmma::fragment<wmma::accumulator, 16, 16, 8, float> acc[4][2];
#pragma unroll
        for (int i = 0; i < 4; i++)
#pragma unroll
            for (int j = 0; j < 2; j++) wmma::fill_fragment(acc[i][j], 0.f);

        for (int k0 = 0; k0 < D_; k0 += 32) {
#pragma unroll
            for (int it = 0; it < 4; it++) {
                int idx = tid + it * 256;
                int r = idx >> 3, c = (idx & 7) * 4;
                float4 va = *reinterpret_cast<const float4*>(
                    embedding + (size_t)toks[r] * D_ + k0 + c);
                As[r * 36 + c] = totf(va.x); As[r * 36 + c + 1] = totf(va.y);
                As[r * 36 + c + 2] = totf(va.z); As[r * 36 + c + 3] = totf(va.w);
                float4 vb = *reinterpret_cast<const float4*>(
                    Wih0 + (size_t)(n0 + r) * D_ + k0 + c);
                Bs[r * 36 + c] = totf(vb.x); Bs[r * 36 + c + 1] = totf(vb.y);
                Bs[r * 36 + c + 2] = totf(vb.z); Bs[r * 36 + c + 3] = totf(vb.w);
            }
            __syncthreads();
#pragma unroll
            for (int kk = 0; kk < 4; kk++) {
                wmma::fragment<wmma::matrix_b, 16, 16, 8, wmma::precision::tf32, wmma::col_major> b[2];
#pragma unroll
                for (int j = 0; j < 2; j++)
                    wmma::load_matrix_sync(b[j], Bs + (wn + j * 16) * 36 + kk * 8, 36);
#pragma unroll
                for (int i = 0; i < 4; i++) {
                    wmma::fragment<wmma::matrix_a, 16, 16, 8, wmma::precision::tf32, wmma::row_major> a;
                    wmma::load_matrix_sync(a, As + (wm + i * 16) * 36 + kk * 8, 36);
#pragma unroll
                    for (int j = 0; j < 2; j++) wmma::mma_sync(acc[i][j], a, b[j], acc[i][j]);
                }
            }
            __syncthreads();
        }
#pragma unroll
        for (int i = 0; i < 4; i++)
#pragma unroll
            for (int j = 0; j < 2; j++) {
                wmma::store_matrix_sync(scr + w * 320, acc[i][j], 20, wmma::mem_row_major);
                __syncwarp();
                int c = lane >> 1;
                int r0 = (lane & 1) * 8;
                int n = n0 + wn + j * 16 + c;
                int mbase = m0 + wm + i * 16 + r0;
                int t = mbase >> 5, b0 = mbase & 31;
                float bias = bsh[wn + j * 16 + c];
                float* dst = g_pre0 + ((size_t)t * G4_ + n) * B_ + b0;
#pragma unroll
                for (int rr = 0; rr < 8; rr++)
                    dst[rr] = scr[w * 320 + (r0 + rr) * 20 + c] + bias;
                __syncwarp();
            }
    } else {
        // ===== C2 = context @ W_attn_in, tile m128 x n128 x k32 =====
        float* As = dsm;                  // 128*36
        float* Bs = dsm + 4608;           // 32*132
        const int bid = blockIdx.x - 256;
        const int m0 = (bid >> 2) * 128, n0 = (bid & 3) * 128;
        const int wm = (w >> 2) * 64, wn = (w & 3) * 32;

        wmma::fragment<wmma::accumulator, 16, 16, 8, float> acc[4][2];
#pragma unroll
        for (int i = 0; i < 4; i++)
#pragma unroll
            for (int j = 0; j < 2; j++) wmma::fill_fragment(acc[i][j], 0.f);

        for (int k0 = 0; k0 < H_; k0 += 32) {
#pragma unroll
            for (int it = 0; it < 4; it++) {
                int idx = tid + it * 256;
                int r = idx >> 3, c = (idx & 7) * 4;
                float4 va = *reinterpret_cast<const float4*>(
                    ctx + (size_t)(m0 + r) * H_ + k0 + c);
                As[r * 36 + c] = totf(va.x); As[r * 36 + c + 1] = totf(va.y);
                As[r * 36 + c + 2] = totf(va.z); As[r * 36 + c + 3] = totf(va.w);
            }
#pragma unroll
            for (int it = 0; it < 4; it++) {
                int idx = tid + it * 256;
                int r = idx >> 5, c = (idx & 31) * 4;
                float4 vb = *reinterpret_cast<const float4*>(
                    Wq + (size_t)(k0 + r) * H_ + n0 + c);
                Bs[r * 132 + c] = totf(vb.x); Bs[r * 132 + c + 1] = totf(vb.y);
                Bs[r * 132 + c + 2] = totf(vb.z); Bs[r * 132 + c + 3] = totf(vb.w);
            }
            __syncthreads();
#pragma unroll
            for (int kk = 0; kk < 4; kk++) {
                wmma::fragment<wmma::matrix_b, 16, 16, 8, wmma::precision::tf32, wmma::row_major> b[2];
#pragma unroll
                for (int j = 0; j < 2; j++)
                    wmma::load_matrix_sync(b[j], Bs + kk * 8 * 132 + wn + j * 16, 132);
#pragma unroll
                for (int i = 0; i < 4; i++) {
                    wmma::fragment<wmma::matrix_a, 16, 16, 8, wmma::precision::tf32, wmma::row_major> a;
                    wmma::load_matrix_sync(a, As + (wm + i * 16) * 36 + kk * 8, 36);
#pragma unroll
                    for (int j = 0; j < 2; j++) wmma::mma_sync(acc[i][j], a, b[j], acc[i][j]);
                }
            }
            __syncthreads();
        }
#pragma unroll
        for (int i = 0; i < 4; i++)
#pragma unroll
            for (int j = 0; j < 2; j++)
                wmma::store_matrix_sync(g_c2 + (size_t)(m0 + wm + i * 16) * H_ + n0 + wn + j * 16,
                                        acc[i][j], H_, wmma::mem_row_major);
    }
}

// ---------------- pipelined persistent scan kernel ---------------------------
// SMEM float offsets
#define SM_W0    0                          // 16 x 520
#define SM_W1    8320                       // 16 x 1040
#define SM_WOS   24960                      // 4 x 1024
#define SM_STAGE 29056                      // 32 x 520
#define SM_PBUF0 45696                      // 8 x 256
#define SM_PBUF1 47744                      // 8 x 256
#define SM_CB    49792                      // 2 x 4 x 32
#define SM_B1    50048                      // 16
#define SM_PART  50064                      // 4 x 8 x 32 = 1024
#define SM_SC    51088                      // 64
#define SM_ATT   51152                      // 64
#define SMEM_FLOATS 51216
#define SMEM_BYTES  (SMEM_FLOATS * 4)

#define LDW0  520
#define LDW1  1040
#define LDST  520

__device__ __forceinline__ void gridbar(unsigned target) {
    __threadfence();
    __syncthreads();
    if (threadIdx.x == 0) {
        atomicAdd(&g_bar, 1u);
        volatile unsigned* vb = &g_bar;
        while (*vb < target) __nanosleep(32);
    }
    __syncthreads();
}

// copy 32x512 row-major h into padded stage [b][520], rounding to tf32
__device__ __forceinline__ void stage_rows(float* stg, const float4* src, int tid) {
    for (int idx = tid; idx < 4096; idx += 256) {
        int b = idx >> 7, j = idx & 127;
        float4 v = __ldcg(&src[idx]);
        v.x = totf(v.x); v.y = totf(v.y); v.z = totf(v.z); v.w = totf(v.w);
        reinterpret_cast<float4*>(stg + b * LDST)[j] = v;
    }
}

__global__ void __launch_bounds__(256, 1)
k_scan(const float* __restrict__ Whh0, const float* __restrict__ Wih1,
       const float* __restrict__ Whh1, const float* __restrict__ bih,
       const float* __restrict__ bhh, const float* __restrict__ context,
       const float* __restrict__ Wout, const float* __restrict__ h0in,
       const float* __restrict__ c0in, float* __restrict__ out) {
    extern __shared__ float sm[];
    float*  W0s   = sm + SM_W0;
    float*  W1s   = sm + SM_W1;
    float*  Wos   = sm + SM_WOS;
    float*  stg   = sm + SM_STAGE;
    float*  pbuf0 = sm + SM_PBUF0;
    float*  pbuf1 = sm + SM_PBUF1;
    float*  cb    = sm + SM_CB;
    float*  bias1 = sm + SM_B1;
    float*  part  = sm + SM_PART;
    float*  sc    = sm + SM_SC;
    float*  att   = sm + SM_ATT;

    const int cta = blockIdx.x;
    const int tid = threadIdx.x;
    const int w   = tid >> 5;
    const int lane = tid & 31;
    const int u0  = cta * UPC_;
    const int wn  = w & 1;            // n-tile (batch 16s)
    const int wkc = w >> 1;           // k-chunk (128s)
    const int ab  = cta & 31;         // attention batch
    const int aq  = cta >> 5;         // attention quarter (0..3)

    // -------- prologue: weights -> SMEM (pre-rounded to tf32) --------------
    for (int idx = tid; idx < 16 * 128; idx += 256) {
        int r = idx >> 7, kq = idx & 127;
        int row = ((r >> 2) * H_) + u0 + (r & 3);
        float4 v = *reinterpret_cast<const float4*>(Whh0 + (size_t)row * H_ + kq * 4);
        v.x = totf(v.x); v.y = totf(v.y); v.z = totf(v.z); v.w = totf(v.w);
        reinterpret_cast<float4*>(W0s + r * LDW0)[kq] = v;
    }
    for (int idx = tid; idx < 16 * 256; idx += 256) {
        int r = idx >> 8, kq = idx & 255;
        int row = ((r >> 2) * H_) + u0 + (r & 3);
        const float* src = (kq < 128)
            ? (Wih1 + (size_t)row * H_ + kq * 4)
            : (Whh1 + (size_t)row * H_ + (kq - 128) * 4);
        float4 v = *reinterpret_cast<const float4*>(src);
        v.x = totf(v.x); v.y = totf(v.y); v.z = totf(v.z); v.w = totf(v.w);
        reinterpret_cast<float4*>(W1s + r * LDW1)[kq] = v;
    }
    for (int idx = tid; idx < 4 * 256; idx += 256) {     // Wos fp32
        int r = idx >> 8, kq = idx & 255;
        reinterpret_cast<float4*>(Wos + r * 1024)[kq] =
            *reinterpret_cast<const float4*>(Wout + (size_t)(u0 + r) * (2 * H_) + kq * 4);
    }
    if (tid < 16) {
        int row = ((tid >> 2) * H_) + u0 + (tid & 3);
        bias1[tid] = bih[G4_ + row] + bhh[G4_ + row];
    }
    {   // cell state: cb[l*128 + ul*32 + b]
        int l = tid >> 7, ul = (tid >> 5) & 3, b = tid & 31;
        cb[tid] = c0in[(size_t)l * B_ * H_ + (size_t)b * H_ + u0 + ul];
    }
    if (tid < 32) {   // initial h -> slot 1 (read at tick 0 / tick 1)
        int b = tid;
#pragma unroll
        for (int ul = 0; ul < 4; ul++) {
            __stcg(&g_h0[1][b * H_ + u0 + ul], h0in[(size_t)b * H_ + u0 + ul]);
            __stcg(&g_h1[1][b * H_ + u0 + ul], h0in[(size_t)B_ * H_ + b * H_ + u0 + ul]);
        }
    }
    unsigned nbar = 0;
    gridbar(++nbar * CTAS_);

    // -------- pipelined main loop: tick tau computes
    //          L0(t=tau), L1(t=tau-1), attn(t=tau-2), attnout(t=tau-3) -------
    for (int tau = 0; tau < NT_; tau++) {
        const int sh0r = (tau + 1) & 1, sh0w = tau & 1;
        const int sh1r = tau & 1,       sh1w = (tau + 1) & 1;
        const int catw = tau & 1,       catr = (tau + 1) & 1;

        // (a) stage h0out_{tau-1}; prefetch h1out_{tau-2} into registers;
        //     prefetch pre0 gate values for the L0 epilogue
        stage_rows(stg, reinterpret_cast<const float4*>(g_h0[sh0r]), tid);
        float4 pf[16];
        {
            const float4* h1src = reinterpret_cast<const float4*>(g_h1[sh1r]);
#pragma unroll
            for (int q = 0; q < 16; q++) pf[q] = __ldcg(&h1src[tid + q * 256]);
        }
        float preI = 0.f, preF = 0.f, preG = 0.f, preO = 0.f;
        if (tau <= 63 && tid < 128) {
            int ul = tid >> 5, b = tid & 31, u = u0 + ul;
            const float* pre = g_pre0 + (size_t)tau * G4_ * B_;
            preI = __ldg(&pre[((size_t)0 * H_ + u) * B_ + b]);
            preF = __ldg(&pre[((size_t)1 * H_ + u) * B_ + b]);
            preG = __ldg(&pre[((size_t)2 * H_ + u) * B_ + b]);
            preO = __ldg(&pre[((size_t)3 * H_ + u) * B_ + b]);
        }
        __syncthreads();

        // (b) L0 mma (acc0) + L1 pass0 mma (acc1) off the same stage
        wmma::fragment<wmma::accumulator, 16, 16, 8, float> acc0, acc1;
        wmma::fill_fragment(acc0, 0.f);
        wmma::fill_fragment(acc1, 0.f);
#pragma unroll
        for (int kk = 0; kk < 16; kk++) {
            int k = wkc * 128 + kk * 8;
            wmma::fragment<wmma::matrix_b, 16, 16, 8, wmma::precision::tf32, wmma::col_major> b;
            wmma::load_matrix_sync(b, stg + (wn * 16) * LDST + k, LDST);
            wmma::fragment<wmma::matrix_a, 16, 16, 8, wmma::precision::tf32, wmma::row_major> a0, a1;
            wmma::load_matrix_sync(a0, W0s + k, LDW0);
            wmma::load_matrix_sync(a1, W1s + k, LDW1);
            wmma::mma_sync(acc0, a0, b, acc0);
            wmma::mma_sync(acc1, a1, b, acc1);
        }
        __syncthreads();   // done reading stage

        // (c) write prefetched h1 into stage (pure STS)
#pragma unroll
        for (int q = 0; q < 16; q++) {
            int idx = tid + q * 256;
            float4 v = pf[q];
            v.x = totf(v.x); v.y = totf(v.y); v.z = totf(v.z); v.w = totf(v.w);
            reinterpret_cast<float4*>(stg + (idx >> 7) * LDST)[idx & 127] = v;
        }
        __syncthreads();

        // (d) L1 pass1 mma
#pragma unroll
        for (int kk = 0; kk < 16; kk++) {
            int k = wkc * 128 + kk * 8;
            wmma::fragment<wmma::matrix_b, 16, 16, 8, wmma::precision::tf32, wmma::col_major> b;
            wmma::load_matrix_sync(b, stg + (wn * 16) * LDST + k, LDST);
            wmma::fragment<wmma::matrix_a, 16, 16, 8, wmma::precision::tf32, wmma::row_major> a;
            wmma::load_matrix_sync(a, W1s + 512 + k, LDW1);
            wmma::mma_sync(acc1, a, b, acc1);
        }
        wmma::store_matrix_sync(pbuf0 + w * 256, acc0, 16, wmma::mem_row_major);
        wmma::store_matrix_sync(pbuf1 + w * 256, acc1, 16, wmma::mem_row_major);
        __syncthreads();

        // (f) fused reduction+epilogue: L0 on tid<128, L1 on tid>=128
        if (tau <= 63 && tid < 128) {
            int t = tau;
            int ul = tid >> 5, b = tid & 31, u = u0 + ul;
            const int bo = (b >> 4) * 256 + (b & 15);
            float s[4];
#pragma unroll
            for (int g = 0; g < 4; g++) {
                float v = 0.f;
#pragma unroll
                for (int kc = 0; kc < 4; kc++)
                    v += pbuf0[bo + kc * 512 + (g * 4 + ul) * 16];
                s[g] = v;
            }
            float gi = sigf(s[0] + preI);
            float gf = sigf(s[1] + preF);
            float gg = tanhf(s[2] + preG);
            float go = sigf(s[3] + preO);
            float c = gf * cb[ul * 32 + b] + gi * gg;
            cb[ul * 32 + b] = c;
            float h = go * tanhf(c);
            __stcg(&g_h0[sh0w][b * H_ + u], h);
            if (t == T_ - 1) {
                out[OFF_HT + (size_t)b * H_ + u] = h;
                out[OFF_CT + (size_t)b * H_ + u] = c;
            }
        }
        if (tau >= 1 && tau <= 64 && tid >= 128) {
            int t = tau - 1;
            int tt = tid - 128;
            int ul = tt >> 5, b = tt & 31, u = u0 + ul;
            const int bo = (b >> 4) * 256 + (b & 15);
            float s[4];
#pragma unroll
            for (int g = 0; g < 4; g++) {
                float v = 0.f;
#pragma unroll
                for (int kc = 0; kc < 4; kc++)
                    v += pbuf1[bo + kc * 512 + (g * 4 + ul) * 16];
                s[g] = v;
            }
            float gi = sigf(s[0] + bias1[0  + ul]);
            float gf = sigf(s[1] + bias1[4  + ul]);
            float gg = tanhf(s[2] + bias1[8  + ul]);
            float go = sigf(s[3] + bias1[12 + ul]);
            float c = gf * cb[128 + ul * 32 + b] + gi * gg;
            cb[128 + ul * 32 + b] = c;
            float h = go * tanhf(c);
            __stcg(&g_h1[sh1w][b * H_ + u], h);
            if (t == T_ - 1) {
                out[OFF_HT + (size_t)B_ * H_ + (size_t)b * H_ + u] = h;
                out[OFF_CT + (size_t)B_ * H_ + (size_t)b * H_ + u] = c;
            }
        }

        // (g) attention for t = tau-2 (stg holds h1out_{tau-2})
        if (tau >= 2 && tau <= 65) {
            const float4* qs4 = reinterpret_cast<const float4*>(stg + ab * LDST);
#pragma unroll
            for (int si = 0; si < 8; si++) {
                int s = w * 8 + si;
                const float4* c2r = reinterpret_cast<const float4*>(
                    g_c2 + (size_t)(ab * S_ + s) * H_);
                float a = 0.f;
#pragma unroll
                for (int kq = lane; kq < 128; kq += 32) {
                    float4 cv = __ldg(&c2r[kq]);
                    float4 qv = qs4[kq];
                    a += cv.x * qv.x + cv.y * qv.y + cv.z * qv.z + cv.w * qv.w;
                }
#pragma unroll
                for (int off = 16; off; off >>= 1) a += __shfl_xor_sync(0xffffffffu, a, off);
                if (lane == 0) sc[s] = a;
            }
            __syncthreads();
            if (tid < 32) {
                float v0 = sc[tid], v1 = sc[tid + 32];
                float m = fmaxf(v0, v1);
#pragma unroll
                for (int off = 16; off; off >>= 1) m = fmaxf(m, __shfl_xor_sync(0xffffffffu, m, off));
                float e0 = __expf(v0 - m), e1 = __expf(v1 - m);
                float s2 = e0 + e1;
#pragma unroll
                for (int off = 16; off; off >>= 1) s2 += __shfl_xor_sync(0xffffffffu, s2, off);
                float inv = 1.f / s2;
                att[tid] = e0 * inv; att[tid + 32] = e1 * inv;
                if (aq == 0 && tau == 65) {
                    out[OFF_ATTN + ab * S_ + tid]      = e0 * inv;
                    out[OFF_ATTN + ab * S_ + tid + 32] = e1 * inv;
                }
            }
            __syncthreads();
            {   // ctx: quarter handles h in [aq*128, aq*128+128); 2 threads per h
                int h = aq * 128 + (tid >> 1);
                int s0 = (tid & 1) * 32;
                const float* cx = context + (size_t)ab * S_ * H_ + h;
                float a = 0.f;
#pragma unroll 8
                for (int s = s0; s < s0 + 32; s++) a += att[s] * cx[(size_t)s * H_];
                a += __shfl_xor_sync(0xffffffffu, a, 1);
                if ((tid & 1) == 0) {
                    float* catp = reinterpret_cast<float*>(g_cat4[catw]);
                    __stcg(&catp[((h >> 2) * 32 + ab) * 4 + (h & 3)], a);
                    int h2 = H_ + h;
                    float hv = __ldcg(&g_h1[sh1r][ab * H_ + h]);
                    __stcg(&catp[((h2 >> 2) * 32 + ab) * 4 + (h2 & 3)], hv);
                }
            }
        }

        // (h) attention-out for t = tau-3: warp w owns k-quads [w*16, w*16+16)
        if (tau >= 3) {
            const int tO = tau - 3;
            float racc[4] = {0.f, 0.f, 0.f, 0.f};
            const int i0 = w * 16;
#pragma unroll
            for (int half = 0; half < 2; half++) {
                const float4* catp = g_cat4[catr] + half * 4096;
                const float4* wr = reinterpret_cast<const float4*>(Wos + half * H_);
#pragma unroll 4
                for (int i = 0; i < 16; i++) {
                    float4 h = __ldcg(&catp[(i0 + i) * 32 + lane]);
#pragma unroll
                    for (int row = 0; row < 4; row++) {
                        float4 x = wr[row * 256 + i0 + i];
                        racc[row] += x.x * h.x + x.y * h.y + x.z * h.z + x.w * h.w;
                    }
                }
            }
#pragma unroll
            for (int row = 0; row < 4; row++)
                part[row * 256 + w * 32 + lane] = racc[row];
            __syncthreads();
            if (tid < 128) {
                int r = tid >> 5, b = tid & 31;
                float v = 0.f;
#pragma unroll
                for (int ww = 0; ww < 8; ww++) v += part[r * 256 + ww * 32 + b];
                v = tanhf(v);
                g_outs_bf[((size_t)tO * B_ + b) * H_ + u0 + r] = __float2bfloat16(v);
            }
        }

        if (tau != NT_ - 1) gridbar(++nbar * CTAS_);
    }
}

// ---------------- vocab GEMM + fused bias/exp-rowsum epilogue ----------------
// CTA tile 256x128, 512 threads, double-buffered SMEM, k-tile 64
#define WMMA_SMEM ((2 * 256 * 72 + 2 * 128 * 72) * 2)   // 110592 bytes
__global__ void __launch_bounds__(512)
k_wmma(float* __restrict__ C, const float* __restrict__ b_lin) {
    extern __shared__ __align__(16) __nv_bfloat16 wsm[];
    __nv_bfloat16* As = wsm;                      // [2][256*72]
    __nv_bfloat16* Bs = wsm + 2 * 256 * 72;       // [2][128*72]
    const int m0 = blockIdx.y * 256, n0 = blockIdx.x * 128;
    const int tid = threadIdx.x;
    const int wid = tid >> 5;
    const int wm = (wid >> 2) * 64, wn = (wid & 3) * 32;
    wmma::fragment<wmma::accumulator, 16, 16, 16, float> acc[4][2];
#pragma unroll
    for (int i = 0; i < 4; i++)
#pragma unroll
        for (int j = 0; j < 2; j++) wmma::fill_fragment(acc[i][j], 0.f);
    const int ar = tid >> 1, ac = (tid & 1) * 32;   // A: 4 uint4 per thread
    const int br = tid >> 2, bc = (tid & 3) * 16;   // B: 2 uint4 per thread

    // preload k-tile 0
#pragma unroll
    for (int q = 0; q < 4; q++)
        *reinterpret_cast<uint4*>(&As[ar * 72 + ac + q * 8]) =
            *reinterpret_cast<const uint4*>(&g_outs_bf[(size_t)(m0 + ar) * D_ + ac + q * 8]);
#pragma unroll
    for (int q = 0; q < 2; q++)
        *reinterpret_cast<uint4*>(&Bs[br * 72 + bc + q * 8]) =
            *reinterpret_cast<const uint4*>(&g_wlin_bf[(size_t)(n0 + br) * D_ + bc + q * 8]);
    __syncthreads();

    int buf = 0;
    for (int k0 = 0; k0 < D_; k0 += 64) {
        uint4 ra[4], rb[2];
        const bool nx = (k0 + 64 < D_);
        if (nx) {
#pragma unroll
            for (int q = 0; q < 4; q++)
                ra[q] = *reinterpret_cast<const uint4*>(
                    &g_outs_bf[(size_t)(m0 + ar) * D_ + k0 + 64 + ac + q * 8]);
#pragma unroll
            for (int q = 0; q < 2; q++)
                rb[q] = *reinterpret_cast<const uint4*>(
                    &g_wlin_bf[(size_t)(n0 + br) * D_ + k0 + 64 + bc + q * 8]);
        }
        const __nv_bfloat16* Ab = As + buf * (256 * 72);
        const __nv_bfloat16* Bb = Bs + buf * (128 * 72);
#pragma unroll
        for (int sub = 0; sub < 4; sub++) {
            wmma::fragment<wmma::matrix_b, 16, 16, 16, __nv_bfloat16, wmma::col_major> bf[2];
#pragma unroll
            for (int j = 0; j < 2; j++)
                wmma::load_matrix_sync(bf[j], &Bb[(wn + j * 16) * 72 + sub * 16], 72);
#pragma unroll
            for (int i = 0; i < 4; i++) {
                wmma::fragment<wmma::matrix_a, 16, 16, 16, __nv_bfloat16, wmma::row_major> af;
                wmma::load_matrix_sync(af, &Ab[(wm + i * 16) * 72 + sub * 16], 72);
#pragma unroll
                for (int j = 0; j < 2; j++) wmma::mma_sync(acc[i][j], af, bf[j], acc[i][j]);
            }
        }
        if (nx) {
            __nv_bfloat16* Aw = As + (buf ^ 1) * (256 * 72);
            __nv_bfloat16* Bw = Bs + (buf ^ 1) * (128 * 72);
#pragma unroll
            for (int q = 0; q < 4; q++)
                *reinterpret_cast<uint4*>(&Aw[ar * 72 + ac + q * 8]) = ra[q];
#pragma unroll
            for (int q = 0; q < 2; q++)
                *reinterpret_cast<uint4*>(&Bw[br * 72 + bc + q * 8]) = rb[q];
        }
        __syncthreads();
        buf ^= 1;
    }

    // ---- fused epilogue: stage frags -> smem, add bias, store, exp-rowsum ----
    float* fsm = reinterpret_cast<float*>(wsm);   // reuse as [128][132] scratch
#pragma unroll
    for (int p = 0; p < 2; p++) {
        __syncthreads();
#pragma unroll
        for (int k2 = 0; k2 < 2; k2++) {
            int i = 2 * p + k2;
            int srow = (wm >> 1) + k2 * 16;
#pragma unroll
            for (int j = 0; j < 2; j++)
                wmma::store_matrix_sync(fsm + (size_t)srow * 132 + wn + j * 16,
                                        acc[i][j], 132, wmma::mem_row_major);
        }
        __syncthreads();
        int r2 = tid >> 2;                         // smem row 0..127
        int g = r2 >> 5;
        int grow = g * 64 + p * 32 + (r2 & 31);    // row within 256-tile
        size_t gr = (size_t)(m0 + grow);
        float sum = 0.f;
        float* crow = C + gr * V_ + n0;
#pragma unroll
        for (int q = 0; q < 8; q++) {
            int cc = (tid & 3) * 4 + q * 16;
            float4 v = *reinterpret_cast<float4*>(&fsm[r2 * 132 + cc]);
            float4 bb = *reinterpret_cast<const float4*>(&b_lin[n0 + cc]);
            v.x += bb.x; v.y += bb.y; v.z += bb.z; v.w += bb.w;
            *reinterpret_cast<float4*>(&crow[cc]) = v;
            sum += __expf(v.x) + __expf(v.y) + __expf(v.z) + __expf(v.w);
        }
        sum += __shfl_xor_sync(0xffffffffu, sum, 1);
        sum += __shfl_xor_sync(0xffffffffu, sum, 2);
        if ((tid & 3) == 0) atomicAdd(&g_rowsum[gr], sum);
    }
}

// ---------------- final: subtract lse (logits already biased) ----------------
__global__ void k_lsm(float* __restrict__ logits) {
    const int row = blockIdx.x;
    const float lse = logf(g_rowsum[row]);
    float4* p4 = reinterpret_cast<float4*>(logits + (size_t)row * V_);
    for (int v = threadIdx.x; v < V_ / 4; v += 256) {
        float4 x = p4[v];
        x.x -= lse; x.y -= lse; x.z -= lse; x.w -= lse;
        p4[v] = x;
    }
}

// ---------------- host driver ----------------------------------------------
extern "C" void kernel_launch(void* const* d_in, const int* in_sizes, int n_in,
                              void* d_out, int out_size) {
    const int*   tokens     = (const int*)d_in[0];
    const float* h0         = (const float*)d_in[1];
    const float* c0         = (const float*)d_in[2];
    const float* context    = (const float*)d_in[3];
    const float* embedding  = (const float*)d_in[4];
    const float* Wih        = (const float*)d_in[5];
    const float* Whh        = (const float*)d_in[6];
    const float* bih        = (const float*)d_in[7];
    const float* bhh        = (const float*)d_in[8];
    const float* W_attn_in  = (const float*)d_in[9];
    const float* W_attn_out = (const float*)d_in[10];
    const float* W_lin      = (const float*)d_in[11];
    const float* b_lin      = (const float*)d_in[12];
    float* out = (float*)d_out;

    cudaFuncSetAttribute(k_scan, cudaFuncAttributeMaxDynamicSharedMemorySize, SMEM_BYTES);
    cudaFuncSetAttribute(k_wmma, cudaFuncAttributeMaxDynamicSharedMemorySize, WMMA_SMEM);
    cudaFuncSetAttribute(k_prolog, cudaFuncAttributeMaxDynamicSharedMemorySize, PRE_SMEM);

    const float* Wih1 = Wih + (size_t)G4_ * D_;
    const float* Whh1 = Whh + (size_t)G4_ * H_;

    k_convert_wlin<<<(V_ * D_ / 4 + 255) / 256, 256>>>(W_lin);
    k_prolog<<<320, 256, PRE_SMEM>>>(tokens, embedding, Wih, bih, bhh,
                                     context, W_attn_in);
    k_scan<<<CTAS_, 256, SMEM_BYTES>>>(Whh, Wih1, Whh1, bih, bhh, context,
                                       W_attn_out, h0, c0, out);
    k_wmma<<<dim3(V_ / 128, MR_ / 256), 512, WMMA_SMEM>>>(out, b_lin);
    k_lsm<<<MR_, 256>>>(out);
}